// round 2
// baseline (speedup 1.0000x reference)
#include <cuda_runtime.h>
#include <math.h>

#define BATCH 4096
#define LEN   8192
#define NF    2112
#define MIDD  264
#define PP    88

// Scratch (allocation-free rule: device globals)
__device__ float g_scale2[BATCH];
__device__ float g_feat[(size_t)BATCH * NF];
__device__ float g_xi  [(size_t)BATCH * NF];
__device__ float g_m   [BATCH * MIDD];
__device__ float g_h1  [BATCH * MIDD];
__device__ float g_h2  [BATCH * PP];

// ---------------------------------------------------------------------------
// Kernel 1: per-row nonzero count -> scale^2
// ---------------------------------------------------------------------------
__global__ void count_kernel(const float* __restrict__ x)
{
    int b = blockIdx.x;
    const float4* row = (const float4*)(x + (size_t)b * LEN);
    int cnt = 0;
    for (int i = threadIdx.x; i < LEN / 4; i += 256) {
        float4 v = row[i];
        cnt += (v.x != 0.0f) + (v.y != 0.0f) + (v.z != 0.0f) + (v.w != 0.0f);
    }
    #pragma unroll
    for (int o = 16; o > 0; o >>= 1) cnt += __shfl_down_sync(0xffffffffu, cnt, o);
    __shared__ int ws[8];
    if ((threadIdx.x & 31) == 0) ws[threadIdx.x >> 5] = cnt;
    __syncthreads();
    if (threadIdx.x == 0) {
        int t = 0;
        #pragma unroll
        for (int i = 0; i < 8; i++) t += ws[i];
        float s = (float)LEN / (float)(t + 1);
        g_scale2[b] = s * s;
    }
}

// ---------------------------------------------------------------------------
// Generic 64x64 tiled fp32 GEMM, BK=8, 256 threads, 4x4 register blocking.
// TB=1: B is [N,K] (C = A @ B^T, "NT").  TB=0: B is [K,N] ("NN").
// EPI: 0 fourier feat    : C = aux0[row] * (acc0^2 + acc1^2)   (dual-B: B0,B1)
//      1 m0              : C = relu(10*acc)
//      2 xi update       : C = 1.6*acc + c0*aux0[idx] + c1*aux1[idx]
//      3 m update        : C = relu(-8*acc + 0.2*aux0[idx])
//      4 relu + bias     : C = relu(acc + aux0[col])
//      6 sigmoid + bias  : C = sigmoid(acc + aux0[col])
// M must be a multiple of 64; K a multiple of 8; N arbitrary (guarded).
// ---------------------------------------------------------------------------
template<int TB, int EPI>
__global__ void gemm64(const float* __restrict__ A, const float* __restrict__ B0,
                       const float* __restrict__ B1, float* __restrict__ C,
                       int N, int K, int lda, int ldb, int ldc,
                       const float* __restrict__ aux0, const float* __restrict__ aux1,
                       float c0, float c1)
{
    __shared__ __align__(16) float As [8][68];
    __shared__ __align__(16) float Bs0[8][68];
    __shared__ __align__(16) float Bs1[8][68];

    const int t  = threadIdx.x;
    const int tx = t & 15;
    const int ty = t >> 4;
    const int m0 = blockIdx.y * 64;
    const int n0 = blockIdx.x * 64;

    float acc0[4][4];
    float acc1[4][4];
    #pragma unroll
    for (int i = 0; i < 4; i++)
        #pragma unroll
        for (int j = 0; j < 4; j++) { acc0[i][j] = 0.0f; acc1[i][j] = 0.0f; }

    const int arow = t >> 2;          // 0..63
    const int ak   = (t & 3) * 2;     // 0,2,4,6
    const int bkr  = t >> 5;          // 0..7  (NN)
    const int bj   = (t & 31) * 2;    // 0..62 (NN)

    for (int k0 = 0; k0 < K; k0 += 8) {
        // ---- load A tile (transposed into smem) ----
        {
            float2 av = *(const float2*)(A + (size_t)(m0 + arow) * lda + k0 + ak);
            As[ak][arow] = av.x; As[ak + 1][arow] = av.y;
        }
        // ---- load B tile(s) ----
        if (TB) {  // NT: B is [N,K]
            int n = n0 + arow;
            float2 bv = make_float2(0.0f, 0.0f);
            if (n < N) bv = *(const float2*)(B0 + (size_t)n * ldb + k0 + ak);
            Bs0[ak][arow] = bv.x; Bs0[ak + 1][arow] = bv.y;
            if (EPI == 0) {
                float2 cv = make_float2(0.0f, 0.0f);
                if (n < N) cv = *(const float2*)(B1 + (size_t)n * ldb + k0 + ak);
                Bs1[ak][arow] = cv.x; Bs1[ak + 1][arow] = cv.y;
            }
        } else {   // NN: B is [K,N]
            float2 bv = make_float2(0.0f, 0.0f);
            if (n0 + bj < N) bv = *(const float2*)(B0 + (size_t)(k0 + bkr) * ldb + n0 + bj);
            Bs0[bkr][bj] = bv.x; Bs0[bkr][bj + 1] = bv.y;
        }
        __syncthreads();

        // ---- compute ----
        #pragma unroll
        for (int kk = 0; kk < 8; kk++) {
            float4 a = *(const float4*)&As [kk][ty * 4];
            float4 b = *(const float4*)&Bs0[kk][tx * 4];
            float av4[4] = {a.x, a.y, a.z, a.w};
            float bv4[4] = {b.x, b.y, b.z, b.w};
            #pragma unroll
            for (int i = 0; i < 4; i++)
                #pragma unroll
                for (int j = 0; j < 4; j++)
                    acc0[i][j] += av4[i] * bv4[j];
            if (EPI == 0) {
                float4 b2 = *(const float4*)&Bs1[kk][tx * 4];
                float cv4[4] = {b2.x, b2.y, b2.z, b2.w};
                #pragma unroll
                for (int i = 0; i < 4; i++)
                    #pragma unroll
                    for (int j = 0; j < 4; j++)
                        acc1[i][j] += av4[i] * cv4[j];
            }
        }
        __syncthreads();
    }

    // ---- epilogue ----
    #pragma unroll
    for (int i = 0; i < 4; i++) {
        int row = m0 + ty * 4 + i;
        #pragma unroll
        for (int j = 0; j < 4; j++) {
            int col = n0 + tx * 4 + j;
            if (col >= N) continue;
            size_t idx = (size_t)row * ldc + col;
            float v;
            if (EPI == 0) {
                v = aux0[row] * (acc0[i][j] * acc0[i][j] + acc1[i][j] * acc1[i][j]);
            } else if (EPI == 1) {
                v = fmaxf(10.0f * acc0[i][j], 0.0f);
            } else if (EPI == 2) {
                v = 1.6f * acc0[i][j] + c0 * aux0[idx] + c1 * aux1[idx];
            } else if (EPI == 3) {
                v = fmaxf(-8.0f * acc0[i][j] + 0.2f * aux0[idx], 0.0f);
            } else if (EPI == 4) {
                v = fmaxf(acc0[i][j] + aux0[col], 0.0f);
            } else {
                float z = acc0[i][j] + aux0[col];
                v = 1.0f / (1.0f + expf(-z));
            }
            C[idx] = v;
        }
    }
}

// ---------------------------------------------------------------------------
extern "C" void kernel_launch(void* const* d_in, const int* in_sizes, int n_in,
                              void* d_out, int out_size)
{
    const float* input_this = (const float*)d_in[0];
    // d_in[1] = input_prev (unused by reference)
    const float* W_cos = (const float*)d_in[2];
    const float* W_sin = (const float*)d_in[3];
    const float* tmpl  = (const float*)d_in[4];
    const float* W1    = (const float*)d_in[5];
    const float* b1    = (const float*)d_in[6];
    const float* W2    = (const float*)d_in[7];
    const float* b2    = (const float*)d_in[8];
    const float* Wout  = (const float*)d_in[9];
    const float* bout  = (const float*)d_in[10];
    float* out = (float*)d_out;

    float *p_scale2, *p_feat, *p_xi, *p_m, *p_h1, *p_h2;
    cudaGetSymbolAddress((void**)&p_scale2, g_scale2);
    cudaGetSymbolAddress((void**)&p_feat,   g_feat);
    cudaGetSymbolAddress((void**)&p_xi,     g_xi);
    cudaGetSymbolAddress((void**)&p_m,      g_m);
    cudaGetSymbolAddress((void**)&p_h1,     g_h1);
    cudaGetSymbolAddress((void**)&p_h2,     g_h2);

    dim3 blk(256);

    // 1. scale^2 per row
    count_kernel<<<BATCH, blk>>>(input_this);

    // 2. feat = scale^2 * ((x@Wc^T)^2 + (x@Ws^T)^2)   [NT, dual-B]
    gemm64<1, 0><<<dim3(NF / 64, BATCH / 64), blk>>>(
        input_this, W_cos, W_sin, p_feat,
        NF, LEN, LEN, LEN, NF, p_scale2, nullptr, 0.f, 0.f);

    // 3. m = relu(10 * feat @ template)   [NN]
    gemm64<0, 1><<<dim3((MIDD + 63) / 64, BATCH / 64), blk>>>(
        p_feat, tmpl, nullptr, p_m,
        MIDD, NF, NF, MIDD, MIDD, nullptr, nullptr, 0.f, 0.f);

    // 4. LISTA iterations
    for (int it = 0; it < 4; it++) {
        // xi = 1.6*(m@T^T) + c0*feat + c1*xi_old   (xi0 = -feat folded into c0)
        float c0 = (it == 0) ? -1.8f : -1.6f;
        float c1 = (it == 0) ?  0.0f :  0.2f;
        gemm64<1, 2><<<dim3(NF / 64, BATCH / 64), blk>>>(
            p_m, tmpl, nullptr, p_xi,
            NF, MIDD, MIDD, MIDD, NF, p_feat, p_xi, c0, c1);
        // m = relu(-8*(xi@T) + 0.2*m)   [NN]
        gemm64<0, 3><<<dim3((MIDD + 63) / 64, BATCH / 64), blk>>>(
            p_xi, tmpl, nullptr, p_m,
            MIDD, NF, NF, MIDD, MIDD, p_m, nullptr, 0.f, 0.f);
    }

    // 5. h1 = relu(m @ W1^T + b1)   [NT]
    gemm64<1, 4><<<dim3((MIDD + 63) / 64, BATCH / 64), blk>>>(
        p_m, W1, nullptr, p_h1,
        MIDD, MIDD, MIDD, MIDD, MIDD, b1, nullptr, 0.f, 0.f);

    // 6. h2 = relu(h1 @ W2^T + b2)  [NT]
    gemm64<1, 4><<<dim3((PP + 63) / 64, BATCH / 64), blk>>>(
        p_h1, W2, nullptr, p_h2,
        PP, MIDD, MIDD, MIDD, PP, b2, nullptr, 0.f, 0.f);

    // 7. out = sigmoid(h2 @ Wout^T + bout)  [NT]
    gemm64<1, 6><<<dim3((PP + 63) / 64, BATCH / 64), blk>>>(
        p_h2, Wout, nullptr, out,
        PP, PP, PP, PP, PP, bout, nullptr, 0.f, 0.f);
}

// round 4
// speedup vs baseline: 2.5242x; 2.5242x over previous
#include <cuda_runtime.h>
#include <cuda_bf16.h>
#include <math.h>
#include <stdint.h>

#define BATCH 4096
#define LEN   8192
#define NF    2112
#define MIDD  264
#define PP    88
#define NW    (2 * NF)     // interleaved cos/sin rows = 4224

// ---------------------------------------------------------------------------
// Device scratch (allocation-free rule)
// ---------------------------------------------------------------------------
__device__ float g_scale2[BATCH];
__device__ float g_feat[(size_t)BATCH * NF];
__device__ float g_xi  [(size_t)BATCH * NF];
__device__ float g_m   [BATCH * MIDD];
__device__ float g_h1  [BATCH * MIDD];
__device__ float g_h2  [BATCH * PP];

__device__ __nv_bfloat16 g_xhi[(size_t)BATCH * LEN];
__device__ __nv_bfloat16 g_xlo[(size_t)BATCH * LEN];
__device__ __nv_bfloat16 g_whi[(size_t)NW * LEN];   // interleaved: row 2f=cos_f, 2f+1=sin_f
__device__ __nv_bfloat16 g_wlo[(size_t)NW * LEN];

// ---------------------------------------------------------------------------
// small PTX helpers (all sm_80-era, legal on base sm_103 target)
// ---------------------------------------------------------------------------
__device__ __forceinline__ uint32_t smem_u32(const void* p) {
    uint32_t a;
    asm("{ .reg .u64 t; cvta.to.shared.u64 t, %1; cvt.u32.u64 %0, t; }" : "=r"(a) : "l"(p));
    return a;
}
__device__ __forceinline__ void cp16(uint32_t saddr, const void* gaddr) {
    asm volatile("cp.async.cg.shared.global [%0], [%1], 16;" :: "r"(saddr), "l"(gaddr));
}
__device__ __forceinline__ void cp_commit() { asm volatile("cp.async.commit_group;"); }
__device__ __forceinline__ void cp_wait1()  { asm volatile("cp.async.wait_group 1;" ::: "memory"); }
__device__ __forceinline__ void cp_wait0()  { asm volatile("cp.async.wait_group 0;" ::: "memory"); }

__device__ __forceinline__ void ldsm4(uint32_t r[4], uint32_t a) {
    asm volatile("ldmatrix.sync.aligned.m8n8.x4.shared.b16 {%0,%1,%2,%3}, [%4];"
                 : "=r"(r[0]), "=r"(r[1]), "=r"(r[2]), "=r"(r[3]) : "r"(a));
}
__device__ __forceinline__ void mma16816(float c[4], const uint32_t a[4],
                                         uint32_t b0, uint32_t b1) {
    asm volatile(
        "mma.sync.aligned.m16n8k16.row.col.f32.bf16.bf16.f32 "
        "{%0,%1,%2,%3}, {%4,%5,%6,%7}, {%8,%9}, {%0,%1,%2,%3};"
        : "+f"(c[0]), "+f"(c[1]), "+f"(c[2]), "+f"(c[3])
        : "r"(a[0]), "r"(a[1]), "r"(a[2]), "r"(a[3]), "r"(b0), "r"(b1));
}

// ---------------------------------------------------------------------------
// per-row nonzero count -> scale^2
// ---------------------------------------------------------------------------
__global__ void count_kernel(const float* __restrict__ x)
{
    int b = blockIdx.x;
    const float4* row = (const float4*)(x + (size_t)b * LEN);
    int cnt = 0;
    for (int i = threadIdx.x; i < LEN / 4; i += 256) {
        float4 v = row[i];
        cnt += (v.x != 0.0f) + (v.y != 0.0f) + (v.z != 0.0f) + (v.w != 0.0f);
    }
    #pragma unroll
    for (int o = 16; o > 0; o >>= 1) cnt += __shfl_down_sync(0xffffffffu, cnt, o);
    __shared__ int ws[8];
    if ((threadIdx.x & 31) == 0) ws[threadIdx.x >> 5] = cnt;
    __syncthreads();
    if (threadIdx.x == 0) {
        int t = 0;
        #pragma unroll
        for (int i = 0; i < 8; i++) t += ws[i];
        float s = (float)LEN / (float)(t + 1);
        g_scale2[b] = s * s;
    }
}

// ---------------------------------------------------------------------------
// fp32 -> bf16 hi/lo split helpers
// ---------------------------------------------------------------------------
__device__ __forceinline__ void split4(float4 v, uint2& hi, uint2& lo)
{
    float f[4] = {v.x, v.y, v.z, v.w};
    uint32_t hb[4], lb[4];
    #pragma unroll
    for (int j = 0; j < 4; j++) {
        __nv_bfloat16 h = __float2bfloat16(f[j]);
        float r = f[j] - __bfloat162float(h);
        __nv_bfloat16 l = __float2bfloat16(r);
        hb[j] = (uint32_t)__bfloat16_as_ushort(h);
        lb[j] = (uint32_t)__bfloat16_as_ushort(l);
    }
    hi = make_uint2(hb[0] | (hb[1] << 16), hb[2] | (hb[3] << 16));
    lo = make_uint2(lb[0] | (lb[1] << 16), lb[2] | (lb[3] << 16));
}

__global__ void split_x_kernel(const float* __restrict__ src, int n4)
{
    int i = blockIdx.x * blockDim.x + threadIdx.x;
    if (i >= n4) return;
    uint2 h, l;
    split4(((const float4*)src)[i], h, l);
    ((uint2*)g_xhi)[i] = h;
    ((uint2*)g_xlo)[i] = l;
}

// interleave cos/sin rows while splitting
__global__ void split_w_kernel(const float* __restrict__ wc, const float* __restrict__ ws)
{
    int i = blockIdx.x * blockDim.x + threadIdx.x;   // over NF * LEN/4
    if (i >= NF * (LEN / 4)) return;
    int f  = i / (LEN / 4);
    int kq = i % (LEN / 4);
    uint2 h, l;
    split4(((const float4*)wc)[i], h, l);
    size_t oc = (size_t)(2 * f) * (LEN / 4) + kq;
    ((uint2*)g_whi)[oc] = h;
    ((uint2*)g_wlo)[oc] = l;
    split4(((const float4*)ws)[i], h, l);
    size_t os = (size_t)(2 * f + 1) * (LEN / 4) + kq;
    ((uint2*)g_whi)[os] = h;
    ((uint2*)g_wlo)[os] = l;
}

// ---------------------------------------------------------------------------
// Fourier GEMM via HMMA (mma.sync bf16, 2-way split, 3 passes)
// C[4096 x 4224] never materialized: epilogue folds pairs into feat.
// CTA: 128(M) x 128(N-cols), K chunks of 64, cp.async double buffer.
// 8 warps: (wid>>2) in M (2 x 64), (wid&3) in N (4 x 32).
// ---------------------------------------------------------------------------
#define KC       64
#define TILE_B   (128 * KC * 2)         // 16384 bytes per bf16 tile
#define STAGE_B  (4 * TILE_B)           // Ahi, Alo, Bhi, Blo
#define FSMEM    (2 * STAGE_B)          // 131072

__device__ __forceinline__ void load_chunk(uint32_t sbase, int m0, int n0, int k0, int tid)
{
    const __nv_bfloat16* srcs[4] = {
        g_xhi + (size_t)m0 * LEN, g_xlo + (size_t)m0 * LEN,
        g_whi + (size_t)n0 * LEN, g_wlo + (size_t)n0 * LEN };
    #pragma unroll
    for (int t = 0; t < 4; t++) {
        uint32_t tb = sbase + t * TILE_B;
        #pragma unroll
        for (int j = 0; j < 4; j++) {
            int c  = tid + j * 256;       // 1024 16B-chunks per tile
            int r  = c >> 3;
            int kc = c & 7;
            const void* g = srcs[t] + (size_t)r * LEN + k0 + kc * 8;
            uint32_t s = tb + r * 128 + (((uint32_t)(kc ^ (r & 7))) << 4);
            cp16(s, g);
        }
    }
}

__global__ __launch_bounds__(256, 1) void fourier_hmma_kernel()
{
    extern __shared__ char smem_raw[];
    const uint32_t sb = smem_u32(smem_raw);

    const int tid  = threadIdx.x;
    const int wid  = tid >> 5;
    const int lane = tid & 31;
    const int wm   = wid >> 2;           // 0..1  -> M offset wm*64
    const int wn   = wid & 3;            // 0..3  -> N offset wn*32
    const int m0   = blockIdx.y * 128;
    const int n0   = blockIdx.x * 128;   // interleaved-col base (grid.x = 33)

    float acc[4][4][4];                  // [mi][ni][frag]
    #pragma unroll
    for (int i = 0; i < 4; i++)
        #pragma unroll
        for (int j = 0; j < 4; j++)
            #pragma unroll
            for (int q = 0; q < 4; q++) acc[i][j][q] = 0.0f;

    // per-lane ldmatrix addressing constants
    const int a_r   = lane & 15;                 // A row within 16-tile
    const int a_k8  = lane >> 4;                 // 0/1 -> +8 k elems
    const uint32_t a_x = (uint32_t)(a_r & 7);    // xor key
    const int bg    = lane >> 3;
    const int b_n   = ((bg >> 1) << 3) + (lane & 7);
    const int b_k8  = bg & 1;
    const uint32_t b_x = (uint32_t)(lane & 7);

    uint32_t a_row_b[4], b_row_b[2];
    #pragma unroll
    for (int mi = 0; mi < 4; mi++) a_row_b[mi] = (uint32_t)(wm * 64 + mi * 16 + a_r) * 128u;
    #pragma unroll
    for (int pr = 0; pr < 2; pr++) b_row_b[pr] = (uint32_t)(wn * 32 + pr * 16 + b_n) * 128u;

    const int NCH = LEN / KC;            // 128
    load_chunk(sb, m0, n0, 0, tid);
    cp_commit();

    for (int i = 0; i < NCH; i++) {
        const uint32_t su = sb + (uint32_t)(i & 1) * STAGE_B;
        if (i + 1 < NCH) {
            load_chunk(sb + (uint32_t)((i + 1) & 1) * STAGE_B, m0, n0, (i + 1) * KC, tid);
            cp_commit();
            cp_wait1();
        } else {
            cp_wait0();
        }
        __syncthreads();

        const uint32_t ah_b = su;
        const uint32_t al_b = su + TILE_B;
        const uint32_t bh_b = su + 2 * TILE_B;
        const uint32_t bl_b = su + 3 * TILE_B;

        #pragma unroll
        for (int ks = 0; ks < KC / 16; ks++) {
            const uint32_t akc = (uint32_t)(ks * 2 + a_k8);
            const uint32_t bkc = (uint32_t)(ks * 2 + b_k8);
            uint32_t ah[4][4], al[4][4];
            #pragma unroll
            for (int mi = 0; mi < 4; mi++) {
                uint32_t off = a_row_b[mi] + ((akc ^ a_x) << 4);
                ldsm4(ah[mi], ah_b + off);
                ldsm4(al[mi], al_b + off);
            }
            uint32_t bh[8], bl[8];
            #pragma unroll
            for (int pr = 0; pr < 2; pr++) {
                uint32_t off = b_row_b[pr] + ((bkc ^ b_x) << 4);
                ldsm4(&bh[pr * 4], bh_b + off);
                ldsm4(&bl[pr * 4], bl_b + off);
            }
            #pragma unroll
            for (int mi = 0; mi < 4; mi++)
                #pragma unroll
                for (int ni = 0; ni < 4; ni++) {
                    mma16816(acc[mi][ni], ah[mi], bh[ni * 2], bh[ni * 2 + 1]);
                    mma16816(acc[mi][ni], ah[mi], bl[ni * 2], bl[ni * 2 + 1]);
                    mma16816(acc[mi][ni], al[mi], bh[ni * 2], bh[ni * 2 + 1]);
                }
        }
        __syncthreads();
    }

    // epilogue: feat = scale2 * (cos^2 + sin^2); pairs live in (c0,c1)/(c2,c3)
    const int qr = lane >> 2;
    const int qc = lane & 3;
    const int fbase = (n0 >> 1) + wn * 16;
    #pragma unroll
    for (int mi = 0; mi < 4; mi++) {
        int row0 = m0 + wm * 64 + mi * 16 + qr;
        int row1 = row0 + 8;
        float s20 = g_scale2[row0];
        float s21 = g_scale2[row1];
        float* o0 = g_feat + (size_t)row0 * NF;
        float* o1 = g_feat + (size_t)row1 * NF;
        #pragma unroll
        for (int ni = 0; ni < 4; ni++) {
            int f = fbase + ni * 4 + qc;
            float c0 = acc[mi][ni][0], c1 = acc[mi][ni][1];
            float c2 = acc[mi][ni][2], c3 = acc[mi][ni][3];
            o0[f] = s20 * (c0 * c0 + c1 * c1);
            o1[f] = s21 * (c2 * c2 + c3 * c3);
        }
    }
}

// ---------------------------------------------------------------------------
// fp32 SIMT GEMM for LISTA / tail (proven in R2)
// ---------------------------------------------------------------------------
template<int TB, int EPI>
__global__ void gemm64(const float* __restrict__ A, const float* __restrict__ B0,
                       float* __restrict__ C,
                       int N, int K, int lda, int ldb, int ldc,
                       const float* __restrict__ aux0, const float* __restrict__ aux1,
                       float c0, float c1)
{
    __shared__ __align__(16) float As [8][68];
    __shared__ __align__(16) float Bs0[8][68];

    const int t  = threadIdx.x;
    const int tx = t & 15;
    const int ty = t >> 4;
    const int m0 = blockIdx.y * 64;
    const int n0 = blockIdx.x * 64;

    float acc0[4][4];
    #pragma unroll
    for (int i = 0; i < 4; i++)
        #pragma unroll
        for (int j = 0; j < 4; j++) acc0[i][j] = 0.0f;

    const int arow = t >> 2;
    const int ak   = (t & 3) * 2;
    const int bkr  = t >> 5;
    const int bj   = (t & 31) * 2;

    for (int k0 = 0; k0 < K; k0 += 8) {
        {
            float2 av = *(const float2*)(A + (size_t)(m0 + arow) * lda + k0 + ak);
            As[ak][arow] = av.x; As[ak + 1][arow] = av.y;
        }
        if (TB) {
            int n = n0 + arow;
            float2 bv = make_float2(0.0f, 0.0f);
            if (n < N) bv = *(const float2*)(B0 + (size_t)n * ldb + k0 + ak);
            Bs0[ak][arow] = bv.x; Bs0[ak + 1][arow] = bv.y;
        } else {
            float2 bv = make_float2(0.0f, 0.0f);
            if (n0 + bj < N) bv = *(const float2*)(B0 + (size_t)(k0 + bkr) * ldb + n0 + bj);
            Bs0[bkr][bj] = bv.x; Bs0[bkr][bj + 1] = bv.y;
        }
        __syncthreads();

        #pragma unroll
        for (int kk = 0; kk < 8; kk++) {
            float4 a = *(const float4*)&As [kk][ty * 4];
            float4 b = *(const float4*)&Bs0[kk][tx * 4];
            float av4[4] = {a.x, a.y, a.z, a.w};
            float bv4[4] = {b.x, b.y, b.z, b.w};
            #pragma unroll
            for (int i = 0; i < 4; i++)
                #pragma unroll
                for (int j = 0; j < 4; j++)
                    acc0[i][j] += av4[i] * bv4[j];
        }
        __syncthreads();
    }

    #pragma unroll
    for (int i = 0; i < 4; i++) {
        int row = m0 + ty * 4 + i;
        #pragma unroll
        for (int j = 0; j < 4; j++) {
            int col = n0 + tx * 4 + j;
            if (col >= N) continue;
            size_t idx = (size_t)row * ldc + col;
            float v;
            if (EPI == 1) {
                v = fmaxf(10.0f * acc0[i][j], 0.0f);
            } else if (EPI == 2) {
                v = 1.6f * acc0[i][j] + c0 * aux0[idx] + c1 * aux1[idx];
            } else if (EPI == 3) {
                v = fmaxf(-8.0f * acc0[i][j] + 0.2f * aux0[idx], 0.0f);
            } else if (EPI == 4) {
                v = fmaxf(acc0[i][j] + aux0[col], 0.0f);
            } else {
                float z = acc0[i][j] + aux0[col];
                v = 1.0f / (1.0f + expf(-z));
            }
            C[idx] = v;
        }
    }
}

// ---------------------------------------------------------------------------
extern "C" void kernel_launch(void* const* d_in, const int* in_sizes, int n_in,
                              void* d_out, int out_size)
{
    const float* input_this = (const float*)d_in[0];
    const float* W_cos = (const float*)d_in[2];
    const float* W_sin = (const float*)d_in[3];
    const float* tmpl  = (const float*)d_in[4];
    const float* W1    = (const float*)d_in[5];
    const float* b1    = (const float*)d_in[6];
    const float* W2    = (const float*)d_in[7];
    const float* b2    = (const float*)d_in[8];
    const float* Wout  = (const float*)d_in[9];
    const float* bout  = (const float*)d_in[10];
    float* out = (float*)d_out;

    float *p_feat, *p_xi, *p_m, *p_h1, *p_h2;
    cudaGetSymbolAddress((void**)&p_feat, g_feat);
    cudaGetSymbolAddress((void**)&p_xi,   g_xi);
    cudaGetSymbolAddress((void**)&p_m,    g_m);
    cudaGetSymbolAddress((void**)&p_h1,   g_h1);
    cudaGetSymbolAddress((void**)&p_h2,   g_h2);

    dim3 blk(256);

    // scale^2
    count_kernel<<<BATCH, blk>>>(input_this);

    // bf16 hi/lo splits (X plain, W interleaved cos/sin)
    split_x_kernel<<<(BATCH * LEN / 4 + 255) / 256, blk>>>(input_this, BATCH * LEN / 4);
    split_w_kernel<<<(NF * LEN / 4 + 255) / 256, blk>>>(W_cos, W_sin);

    // Fourier GEMM via HMMA
    cudaFuncSetAttribute(fourier_hmma_kernel,
                         cudaFuncAttributeMaxDynamicSharedMemorySize, FSMEM);
    fourier_hmma_kernel<<<dim3(NW / 128, BATCH / 128), blk, FSMEM>>>();

    // m = relu(10 * feat @ template)
    gemm64<0, 1><<<dim3((MIDD + 63) / 64, BATCH / 64), blk>>>(
        p_feat, tmpl, p_m, MIDD, NF, NF, MIDD, MIDD, nullptr, nullptr, 0.f, 0.f);

    // LISTA iterations
    for (int it = 0; it < 4; it++) {
        float c0 = (it == 0) ? -1.8f : -1.6f;
        float c1 = (it == 0) ?  0.0f :  0.2f;
        gemm64<1, 2><<<dim3(NF / 64, BATCH / 64), blk>>>(
            p_m, tmpl, p_xi, NF, MIDD, MIDD, MIDD, NF, p_feat, p_xi, c0, c1);
        gemm64<0, 3><<<dim3((MIDD + 63) / 64, BATCH / 64), blk>>>(
            p_xi, tmpl, p_m, MIDD, NF, NF, MIDD, MIDD, p_m, nullptr, 0.f, 0.f);
    }

    // MLP tail
    gemm64<1, 4><<<dim3((MIDD + 63) / 64, BATCH / 64), blk>>>(
        p_m, W1, p_h1, MIDD, MIDD, MIDD, MIDD, MIDD, b1, nullptr, 0.f, 0.f);
    gemm64<1, 4><<<dim3((PP + 63) / 64, BATCH / 64), blk>>>(
        p_h1, W2, p_h2, PP, MIDD, MIDD, MIDD, PP, b2, nullptr, 0.f, 0.f);
    gemm64<1, 6><<<dim3((PP + 63) / 64, BATCH / 64), blk>>>(
        p_h2, Wout, out, PP, PP, PP, PP, PP, bout, nullptr, 0.f, 0.f);
}

// round 5
// speedup vs baseline: 2.7040x; 1.0712x over previous
#include <cuda_runtime.h>
#include <cuda_bf16.h>
#include <math.h>
#include <stdint.h>

#define BATCH 4096
#define LEN   8192
#define NF    2112
#define MIDD  264
#define PP    88
#define NW    (2 * NF)     // interleaved cos/sin rows = 4224

// ---------------------------------------------------------------------------
// Device scratch (allocation-free rule)
// ---------------------------------------------------------------------------
__device__ float g_scale2[BATCH];
__device__ float g_m  [BATCH * MIDD];
__device__ float g_h1 [BATCH * MIDD];
__device__ float g_h2 [BATCH * PP];

__device__ __align__(16) __nv_bfloat16 g_xhi[(size_t)BATCH * LEN];
__device__ __align__(16) __nv_bfloat16 g_xlo[(size_t)BATCH * LEN];
__device__ __align__(16) __nv_bfloat16 g_whi[(size_t)NW * LEN];
__device__ __align__(16) __nv_bfloat16 g_wlo[(size_t)NW * LEN];

__device__ __align__(16) __nv_bfloat16 g_fhi [(size_t)BATCH * NF];   // feat split
__device__ __align__(16) __nv_bfloat16 g_flo [(size_t)BATCH * NF];
__device__ __align__(16) __nv_bfloat16 g_xihi[(size_t)BATCH * NF];   // xi split
__device__ __align__(16) __nv_bfloat16 g_xilo[(size_t)BATCH * NF];
__device__ __align__(16) __nv_bfloat16 g_mhi [(size_t)BATCH * MIDD]; // m split
__device__ __align__(16) __nv_bfloat16 g_mlo [(size_t)BATCH * MIDD];
__device__ __align__(16) __nv_bfloat16 g_thi [(size_t)NF * MIDD];    // template split
__device__ __align__(16) __nv_bfloat16 g_tlo [(size_t)NF * MIDD];
__device__ __align__(16) __nv_bfloat16 g_tthi[(size_t)MIDD * NF];    // template^T split
__device__ __align__(16) __nv_bfloat16 g_ttlo[(size_t)MIDD * NF];

// ---------------------------------------------------------------------------
// PTX helpers (sm_80-era, legal on base sm_103)
// ---------------------------------------------------------------------------
__device__ __forceinline__ uint32_t smem_u32(const void* p) {
    uint32_t a;
    asm("{ .reg .u64 t; cvta.to.shared.u64 t, %1; cvt.u32.u64 %0, t; }" : "=r"(a) : "l"(p));
    return a;
}
__device__ __forceinline__ void cp16(uint32_t saddr, const void* gaddr) {
    asm volatile("cp.async.cg.shared.global [%0], [%1], 16;" :: "r"(saddr), "l"(gaddr));
}
__device__ __forceinline__ void cp16z(uint32_t saddr, const void* gaddr, int valid) {
    asm volatile("cp.async.cg.shared.global [%0], [%1], 16, %2;"
                 :: "r"(saddr), "l"(gaddr), "r"(valid ? 16 : 0));
}
__device__ __forceinline__ void cp_commit() { asm volatile("cp.async.commit_group;"); }
__device__ __forceinline__ void cp_wait1()  { asm volatile("cp.async.wait_group 1;" ::: "memory"); }
__device__ __forceinline__ void cp_wait0()  { asm volatile("cp.async.wait_group 0;" ::: "memory"); }

__device__ __forceinline__ void ldsm4(uint32_t r[4], uint32_t a) {
    asm volatile("ldmatrix.sync.aligned.m8n8.x4.shared.b16 {%0,%1,%2,%3}, [%4];"
                 : "=r"(r[0]), "=r"(r[1]), "=r"(r[2]), "=r"(r[3]) : "r"(a));
}
__device__ __forceinline__ void mma16816(float c[4], const uint32_t a[4],
                                         uint32_t b0, uint32_t b1) {
    asm volatile(
        "mma.sync.aligned.m16n8k16.row.col.f32.bf16.bf16.f32 "
        "{%0,%1,%2,%3}, {%4,%5,%6,%7}, {%8,%9}, {%0,%1,%2,%3};"
        : "+f"(c[0]), "+f"(c[1]), "+f"(c[2]), "+f"(c[3])
        : "r"(a[0]), "r"(a[1]), "r"(a[2]), "r"(a[3]), "r"(b0), "r"(b1));
}

__device__ __forceinline__ void split_store(__nv_bfloat16* hi, __nv_bfloat16* lo,
                                            size_t idx, float v) {
    __nv_bfloat16 h = __float2bfloat16(v);
    hi[idx] = h;
    lo[idx] = __float2bfloat16(v - __bfloat162float(h));
}
__device__ __forceinline__ float split_load(const __nv_bfloat16* hi,
                                            const __nv_bfloat16* lo, size_t idx) {
    return __bfloat162float(hi[idx]) + __bfloat162float(lo[idx]);
}

// ---------------------------------------------------------------------------
// per-row nonzero count -> scale^2
// ---------------------------------------------------------------------------
__global__ void count_kernel(const float* __restrict__ x)
{
    int b = blockIdx.x;
    const float4* row = (const float4*)(x + (size_t)b * LEN);
    int cnt = 0;
    for (int i = threadIdx.x; i < LEN / 4; i += 256) {
        float4 v = row[i];
        cnt += (v.x != 0.0f) + (v.y != 0.0f) + (v.z != 0.0f) + (v.w != 0.0f);
    }
    #pragma unroll
    for (int o = 16; o > 0; o >>= 1) cnt += __shfl_down_sync(0xffffffffu, cnt, o);
    __shared__ int ws[8];
    if ((threadIdx.x & 31) == 0) ws[threadIdx.x >> 5] = cnt;
    __syncthreads();
    if (threadIdx.x == 0) {
        int t = 0;
        #pragma unroll
        for (int i = 0; i < 8; i++) t += ws[i];
        float s = (float)LEN / (float)(t + 1);
        g_scale2[b] = s * s;
    }
}

// ---------------------------------------------------------------------------
// split kernels
// ---------------------------------------------------------------------------
__device__ __forceinline__ void split4(float4 v, uint2& hi, uint2& lo)
{
    float f[4] = {v.x, v.y, v.z, v.w};
    uint32_t hb[4], lb[4];
    #pragma unroll
    for (int j = 0; j < 4; j++) {
        __nv_bfloat16 h = __float2bfloat16(f[j]);
        float r = f[j] - __bfloat162float(h);
        __nv_bfloat16 l = __float2bfloat16(r);
        hb[j] = (uint32_t)__bfloat16_as_ushort(h);
        lb[j] = (uint32_t)__bfloat16_as_ushort(l);
    }
    hi = make_uint2(hb[0] | (hb[1] << 16), hb[2] | (hb[3] << 16));
    lo = make_uint2(lb[0] | (lb[1] << 16), lb[2] | (lb[3] << 16));
}

__global__ void split_x_kernel(const float* __restrict__ src, int n4)
{
    int i = blockIdx.x * blockDim.x + threadIdx.x;
    if (i >= n4) return;
    uint2 h, l;
    split4(((const float4*)src)[i], h, l);
    ((uint2*)g_xhi)[i] = h;
    ((uint2*)g_xlo)[i] = l;
}

__global__ void split_w_kernel(const float* __restrict__ wc, const float* __restrict__ ws)
{
    int i = blockIdx.x * blockDim.x + threadIdx.x;
    if (i >= NF * (LEN / 4)) return;
    int f  = i / (LEN / 4);
    int kq = i % (LEN / 4);
    uint2 h, l;
    split4(((const float4*)wc)[i], h, l);
    size_t oc = (size_t)(2 * f) * (LEN / 4) + kq;
    ((uint2*)g_whi)[oc] = h;
    ((uint2*)g_wlo)[oc] = l;
    split4(((const float4*)ws)[i], h, l);
    size_t os = (size_t)(2 * f + 1) * (LEN / 4) + kq;
    ((uint2*)g_whi)[os] = h;
    ((uint2*)g_wlo)[os] = l;
}

// template split + transposed split
__global__ void split_t_kernel(const float* __restrict__ tmpl)
{
    int i = blockIdx.x * blockDim.x + threadIdx.x;
    if (i >= NF * MIDD) return;
    int r = i / MIDD, c = i % MIDD;
    float x = tmpl[i];
    __nv_bfloat16 h = __float2bfloat16(x);
    __nv_bfloat16 l = __float2bfloat16(x - __bfloat162float(h));
    g_thi[i] = h;  g_tlo[i] = l;
    size_t ti = (size_t)c * NF + r;
    g_tthi[ti] = h;  g_ttlo[ti] = l;
}

// ---------------------------------------------------------------------------
// Shared HMMA machinery: CTA 128x128, K chunks of 64 (bf16), double buffer
// ---------------------------------------------------------------------------
#define KC       64
#define TILE_B   (128 * KC * 2)         // 16384 bytes
#define STAGE_B  (4 * TILE_B)
#define FSMEM    (2 * STAGE_B)          // 131072

// Fourier loader (no bounds except rows are always valid; NW/128 exact)
__device__ __forceinline__ void load_chunk(uint32_t sbase, int m0, int n0, int k0, int tid)
{
    const __nv_bfloat16* srcs[4] = {
        g_xhi + (size_t)m0 * LEN, g_xlo + (size_t)m0 * LEN,
        g_whi + (size_t)n0 * LEN, g_wlo + (size_t)n0 * LEN };
    #pragma unroll
    for (int t = 0; t < 4; t++) {
        uint32_t tb = sbase + t * TILE_B;
        #pragma unroll
        for (int j = 0; j < 4; j++) {
            int c  = tid + j * 256;
            int r  = c >> 3;
            int kc = c & 7;
            const void* g = srcs[t] + (size_t)r * LEN + k0 + kc * 8;
            uint32_t s = tb + r * 128 + (((uint32_t)(kc ^ (r & 7))) << 4);
            cp16(s, g);
        }
    }
}

// Bounded loader for LISTA GEMMs
__device__ __forceinline__ void load_chunk_b(
    uint32_t sbase,
    const __nv_bfloat16* __restrict__ Ahi, const __nv_bfloat16* __restrict__ Alo,
    int lda, int m0,
    const __nv_bfloat16* __restrict__ Bhi, const __nv_bfloat16* __restrict__ Blo,
    int ldb, int n0, int N,
    int k0, int K, int tid)
{
    #pragma unroll
    for (int j = 0; j < 4; j++) {
        int c  = tid + j * 256;
        int r  = c >> 3;
        int kc = c & 7;
        int k  = k0 + kc * 8;
        int kv = (k < K);
        uint32_t soff = (uint32_t)r * 128u + (((uint32_t)(kc ^ (r & 7))) << 4);
        const void* ga = kv ? (const void*)(Ahi + (size_t)(m0 + r) * lda + k) : (const void*)Ahi;
        cp16z(sbase + soff, ga, kv);
        ga = kv ? (const void*)(Alo + (size_t)(m0 + r) * lda + k) : (const void*)Alo;
        cp16z(sbase + TILE_B + soff, ga, kv);
        int nv = kv && (n0 + r < N);
        const void* gb = nv ? (const void*)(Bhi + (size_t)(n0 + r) * ldb + k) : (const void*)Bhi;
        cp16z(sbase + 2 * TILE_B + soff, gb, nv);
        gb = nv ? (const void*)(Blo + (size_t)(n0 + r) * ldb + k) : (const void*)Blo;
        cp16z(sbase + 3 * TILE_B + soff, gb, nv);
    }
}

// ---------------------------------------------------------------------------
// Fourier GEMM via HMMA — epilogue writes feat split
// ---------------------------------------------------------------------------
__global__ __launch_bounds__(256, 1) void fourier_hmma_kernel()
{
    extern __shared__ char smem_raw[];
    const uint32_t sb = smem_u32(smem_raw);

    const int tid  = threadIdx.x;
    const int wid  = tid >> 5;
    const int lane = tid & 31;
    const int wm   = wid >> 2;
    const int wn   = wid & 3;
    const int m0   = blockIdx.y * 128;
    const int n0   = blockIdx.x * 128;

    float acc[4][4][4];
    #pragma unroll
    for (int i = 0; i < 4; i++)
        #pragma unroll
        for (int j = 0; j < 4; j++)
            #pragma unroll
            for (int q = 0; q < 4; q++) acc[i][j][q] = 0.0f;

    const int a_r   = lane & 15;
    const int a_k8  = lane >> 4;
    const uint32_t a_x = (uint32_t)(a_r & 7);
    const int bg    = lane >> 3;
    const int b_n   = ((bg >> 1) << 3) + (lane & 7);
    const int b_k8  = bg & 1;
    const uint32_t b_x = (uint32_t)(lane & 7);

    uint32_t a_row_b[4], b_row_b[2];
    #pragma unroll
    for (int mi = 0; mi < 4; mi++) a_row_b[mi] = (uint32_t)(wm * 64 + mi * 16 + a_r) * 128u;
    #pragma unroll
    for (int pr = 0; pr < 2; pr++) b_row_b[pr] = (uint32_t)(wn * 32 + pr * 16 + b_n) * 128u;

    const int NCH = LEN / KC;
    load_chunk(sb, m0, n0, 0, tid);
    cp_commit();

    for (int i = 0; i < NCH; i++) {
        const uint32_t su = sb + (uint32_t)(i & 1) * STAGE_B;
        if (i + 1 < NCH) {
            load_chunk(sb + (uint32_t)((i + 1) & 1) * STAGE_B, m0, n0, (i + 1) * KC, tid);
            cp_commit();
            cp_wait1();
        } else {
            cp_wait0();
        }
        __syncthreads();

        const uint32_t ah_b = su;
        const uint32_t al_b = su + TILE_B;
        const uint32_t bh_b = su + 2 * TILE_B;
        const uint32_t bl_b = su + 3 * TILE_B;

        #pragma unroll
        for (int ks = 0; ks < KC / 16; ks++) {
            const uint32_t akc = (uint32_t)(ks * 2 + a_k8);
            const uint32_t bkc = (uint32_t)(ks * 2 + b_k8);
            uint32_t ah[4][4], al[4][4];
            #pragma unroll
            for (int mi = 0; mi < 4; mi++) {
                uint32_t off = a_row_b[mi] + ((akc ^ a_x) << 4);
                ldsm4(ah[mi], ah_b + off);
                ldsm4(al[mi], al_b + off);
            }
            uint32_t bh[8], bl[8];
            #pragma unroll
            for (int pr = 0; pr < 2; pr++) {
                uint32_t off = b_row_b[pr] + ((bkc ^ b_x) << 4);
                ldsm4(&bh[pr * 4], bh_b + off);
                ldsm4(&bl[pr * 4], bl_b + off);
            }
            #pragma unroll
            for (int mi = 0; mi < 4; mi++)
                #pragma unroll
                for (int ni = 0; ni < 4; ni++) {
                    mma16816(acc[mi][ni], ah[mi], bh[ni * 2], bh[ni * 2 + 1]);
                    mma16816(acc[mi][ni], ah[mi], bl[ni * 2], bl[ni * 2 + 1]);
                    mma16816(acc[mi][ni], al[mi], bh[ni * 2], bh[ni * 2 + 1]);
                }
        }
        __syncthreads();
    }

    // epilogue: feat = scale2 * (cos^2 + sin^2) -> split bf16
    const int qr = lane >> 2;
    const int qc = lane & 3;
    const int fbase = (n0 >> 1) + wn * 16;
    #pragma unroll
    for (int mi = 0; mi < 4; mi++) {
        int row0 = m0 + wm * 64 + mi * 16 + qr;
        int row1 = row0 + 8;
        float s20 = g_scale2[row0];
        float s21 = g_scale2[row1];
        size_t b0 = (size_t)row0 * NF;
        size_t b1 = (size_t)row1 * NF;
        #pragma unroll
        for (int ni = 0; ni < 4; ni++) {
            int f = fbase + ni * 4 + qc;
            float c0 = acc[mi][ni][0], c1 = acc[mi][ni][1];
            float c2 = acc[mi][ni][2], c3 = acc[mi][ni][3];
            split_store(g_fhi, g_flo, b0 + f, s20 * (c0 * c0 + c1 * c1));
            split_store(g_fhi, g_flo, b1 + f, s21 * (c2 * c2 + c3 * c3));
        }
    }
}

// ---------------------------------------------------------------------------
// LISTA HMMA GEMM: C = epi(A_split @ B_split^T)
// EPI 1: relu(10*acc)                       -> C split + Cf
// EPI 2: 1.6*acc + c0*feat + c1*C_old       -> C split      (aux X = feat)
// EPI 3: relu(-8*acc + 0.2*C_old)           -> C split + Cf
// ---------------------------------------------------------------------------
template<int EPI>
__global__ __launch_bounds__(256, 1) void lista_hmma_kernel(
    const __nv_bfloat16* __restrict__ Ahi, const __nv_bfloat16* __restrict__ Alo, int lda,
    const __nv_bfloat16* __restrict__ Bhi, const __nv_bfloat16* __restrict__ Blo, int ldb,
    int N, int K,
    __nv_bfloat16* __restrict__ Chi, __nv_bfloat16* __restrict__ Clo,
    float* __restrict__ Cf, int ldc,
    const __nv_bfloat16* __restrict__ Xhi, const __nv_bfloat16* __restrict__ Xlo,
    float c0, float c1)
{
    extern __shared__ char smem_raw[];
    const uint32_t sb = smem_u32(smem_raw);

    const int tid  = threadIdx.x;
    const int wid  = tid >> 5;
    const int lane = tid & 31;
    const int wm   = wid >> 2;
    const int wn   = wid & 3;
    const int m0   = blockIdx.y * 128;
    const int n0   = blockIdx.x * 128;

    float acc[4][4][4];
    #pragma unroll
    for (int i = 0; i < 4; i++)
        #pragma unroll
        for (int j = 0; j < 4; j++)
            #pragma unroll
            for (int q = 0; q < 4; q++) acc[i][j][q] = 0.0f;

    const int a_r   = lane & 15;
    const int a_k8  = lane >> 4;
    const uint32_t a_x = (uint32_t)(a_r & 7);
    const int bg    = lane >> 3;
    const int b_n   = ((bg >> 1) << 3) + (lane & 7);
    const int b_k8  = bg & 1;
    const uint32_t b_x = (uint32_t)(lane & 7);

    uint32_t a_row_b[4], b_row_b[2];
    #pragma unroll
    for (int mi = 0; mi < 4; mi++) a_row_b[mi] = (uint32_t)(wm * 64 + mi * 16 + a_r) * 128u;
    #pragma unroll
    for (int pr = 0; pr < 2; pr++) b_row_b[pr] = (uint32_t)(wn * 32 + pr * 16 + b_n) * 128u;

    const int NCH = (K + KC - 1) / KC;
    load_chunk_b(sb, Ahi, Alo, lda, m0, Bhi, Blo, ldb, n0, N, 0, K, tid);
    cp_commit();

    for (int i = 0; i < NCH; i++) {
        const uint32_t su = sb + (uint32_t)(i & 1) * STAGE_B;
        if (i + 1 < NCH) {
            load_chunk_b(sb + (uint32_t)((i + 1) & 1) * STAGE_B,
                         Ahi, Alo, lda, m0, Bhi, Blo, ldb, n0, N, (i + 1) * KC, K, tid);
            cp_commit();
            cp_wait1();
        } else {
            cp_wait0();
        }
        __syncthreads();

        const uint32_t ah_b = su;
        const uint32_t al_b = su + TILE_B;
        const uint32_t bh_b = su + 2 * TILE_B;
        const uint32_t bl_b = su + 3 * TILE_B;

        #pragma unroll
        for (int ks = 0; ks < KC / 16; ks++) {
            const uint32_t akc = (uint32_t)(ks * 2 + a_k8);
            const uint32_t bkc = (uint32_t)(ks * 2 + b_k8);
            uint32_t ah[4][4], al[4][4];
            #pragma unroll
            for (int mi = 0; mi < 4; mi++) {
                uint32_t off = a_row_b[mi] + ((akc ^ a_x) << 4);
                ldsm4(ah[mi], ah_b + off);
                ldsm4(al[mi], al_b + off);
            }
            uint32_t bh[8], bl[8];
            #pragma unroll
            for (int pr = 0; pr < 2; pr++) {
                uint32_t off = b_row_b[pr] + ((bkc ^ b_x) << 4);
                ldsm4(&bh[pr * 4], bh_b + off);
                ldsm4(&bl[pr * 4], bl_b + off);
            }
            #pragma unroll
            for (int mi = 0; mi < 4; mi++)
                #pragma unroll
                for (int ni = 0; ni < 4; ni++) {
                    mma16816(acc[mi][ni], ah[mi], bh[ni * 2], bh[ni * 2 + 1]);
                    mma16816(acc[mi][ni], ah[mi], bl[ni * 2], bl[ni * 2 + 1]);
                    mma16816(acc[mi][ni], al[mi], bh[ni * 2], bh[ni * 2 + 1]);
                }
        }
        __syncthreads();
    }

    // epilogue
    const int qr = lane >> 2;
    const int qc = lane & 3;
    #pragma unroll
    for (int mi = 0; mi < 4; mi++) {
        int rows[2];
        rows[0] = m0 + wm * 64 + mi * 16 + qr;
        rows[1] = rows[0] + 8;
        #pragma unroll
        for (int ni = 0; ni < 4; ni++) {
            int colb = n0 + wn * 32 + ni * 8 + qc * 2;
            #pragma unroll
            for (int h = 0; h < 2; h++) {
                #pragma unroll
                for (int cc = 0; cc < 2; cc++) {
                    int col = colb + cc;
                    if (col >= N) continue;
                    size_t idx = (size_t)rows[h] * ldc + col;
                    float a = acc[mi][ni][h * 2 + cc];
                    float v;
                    if (EPI == 1) {
                        v = fmaxf(10.0f * a, 0.0f);
                    } else if (EPI == 2) {
                        v = 1.6f * a + c0 * split_load(Xhi, Xlo, idx);
                        if (c1 != 0.0f) v += c1 * split_load(Chi, Clo, idx);
                    } else {
                        float mo = split_load(Chi, Clo, idx);
                        v = fmaxf(-8.0f * a + 0.2f * mo, 0.0f);
                    }
                    split_store(Chi, Clo, idx, v);
                    if (EPI == 1 || EPI == 3) Cf[idx] = v;
                }
            }
        }
    }
}

// ---------------------------------------------------------------------------
// fp32 SIMT GEMM (tail only: EPI 4 relu+bias, EPI 6 sigmoid+bias)
// ---------------------------------------------------------------------------
template<int EPI>
__global__ void gemm64(const float* __restrict__ A, const float* __restrict__ B0,
                       float* __restrict__ C,
                       int N, int K, int lda, int ldb, int ldc,
                       const float* __restrict__ bias)
{
    __shared__ __align__(16) float As [8][68];
    __shared__ __align__(16) float Bs0[8][68];

    const int t  = threadIdx.x;
    const int tx = t & 15;
    const int ty = t >> 4;
    const int m0 = blockIdx.y * 64;
    const int n0 = blockIdx.x * 64;

    float acc0[4][4];
    #pragma unroll
    for (int i = 0; i < 4; i++)
        #pragma unroll
        for (int j = 0; j < 4; j++) acc0[i][j] = 0.0f;

    const int arow = t >> 2;
    const int ak   = (t & 3) * 2;

    for (int k0 = 0; k0 < K; k0 += 8) {
        {
            float2 av = *(const float2*)(A + (size_t)(m0 + arow) * lda + k0 + ak);
            As[ak][arow] = av.x; As[ak + 1][arow] = av.y;
        }
        {
            int n = n0 + arow;
            float2 bv = make_float2(0.0f, 0.0f);
            if (n < N) bv = *(const float2*)(B0 + (size_t)n * ldb + k0 + ak);
            Bs0[ak][arow] = bv.x; Bs0[ak + 1][arow] = bv.y;
        }
        __syncthreads();

        #pragma unroll
        for (int kk = 0; kk < 8; kk++) {
            float4 a = *(const float4*)&As [kk][ty * 4];
            float4 b = *(const float4*)&Bs0[kk][tx * 4];
            float av4[4] = {a.x, a.y, a.z, a.w};
            float bv4[4] = {b.x, b.y, b.z, b.w};
            #pragma unroll
            for (int i = 0; i < 4; i++)
                #pragma unroll
                for (int j = 0; j < 4; j++)
                    acc0[i][j] += av4[i] * bv4[j];
        }
        __syncthreads();
    }

    #pragma unroll
    for (int i = 0; i < 4; i++) {
        int row = m0 + ty * 4 + i;
        #pragma unroll
        for (int j = 0; j < 4; j++) {
            int col = n0 + tx * 4 + j;
            if (col >= N) continue;
            size_t idx = (size_t)row * ldc + col;
            float v;
            if (EPI == 4) {
                v = fmaxf(acc0[i][j] + bias[col], 0.0f);
            } else {
                float z = acc0[i][j] + bias[col];
                v = 1.0f / (1.0f + expf(-z));
            }
            C[idx] = v;
        }
    }
}

// ---------------------------------------------------------------------------
extern "C" void kernel_launch(void* const* d_in, const int* in_sizes, int n_in,
                              void* d_out, int out_size)
{
    const float* input_this = (const float*)d_in[0];
    const float* W_cos = (const float*)d_in[2];
    const float* W_sin = (const float*)d_in[3];
    const float* tmpl  = (const float*)d_in[4];
    const float* W1    = (const float*)d_in[5];
    const float* b1    = (const float*)d_in[6];
    const float* W2    = (const float*)d_in[7];
    const float* b2    = (const float*)d_in[8];
    const float* Wout  = (const float*)d_in[9];
    const float* bout  = (const float*)d_in[10];
    float* out = (float*)d_out;

    float *p_m, *p_h1, *p_h2;
    cudaGetSymbolAddress((void**)&p_m,  g_m);
    cudaGetSymbolAddress((void**)&p_h1, g_h1);
    cudaGetSymbolAddress((void**)&p_h2, g_h2);
    __nv_bfloat16 *p_fhi, *p_flo, *p_xihi, *p_xilo, *p_mhi, *p_mlo;
    __nv_bfloat16 *p_thi, *p_tlo, *p_tthi, *p_ttlo;
    cudaGetSymbolAddress((void**)&p_fhi,  g_fhi);
    cudaGetSymbolAddress((void**)&p_flo,  g_flo);
    cudaGetSymbolAddress((void**)&p_xihi, g_xihi);
    cudaGetSymbolAddress((void**)&p_xilo, g_xilo);
    cudaGetSymbolAddress((void**)&p_mhi,  g_mhi);
    cudaGetSymbolAddress((void**)&p_mlo,  g_mlo);
    cudaGetSymbolAddress((void**)&p_thi,  g_thi);
    cudaGetSymbolAddress((void**)&p_tlo,  g_tlo);
    cudaGetSymbolAddress((void**)&p_tthi, g_tthi);
    cudaGetSymbolAddress((void**)&p_ttlo, g_ttlo);

    dim3 blk(256);

    count_kernel<<<BATCH, blk>>>(input_this);
    split_x_kernel<<<(BATCH * LEN / 4 + 255) / 256, blk>>>(input_this, BATCH * LEN / 4);
    split_w_kernel<<<(NF * LEN / 4 + 255) / 256, blk>>>(W_cos, W_sin);
    split_t_kernel<<<(NF * MIDD + 255) / 256, blk>>>(tmpl);

    cudaFuncSetAttribute(fourier_hmma_kernel,
                         cudaFuncAttributeMaxDynamicSharedMemorySize, FSMEM);
    cudaFuncSetAttribute(lista_hmma_kernel<1>,
                         cudaFuncAttributeMaxDynamicSharedMemorySize, FSMEM);
    cudaFuncSetAttribute(lista_hmma_kernel<2>,
                         cudaFuncAttributeMaxDynamicSharedMemorySize, FSMEM);
    cudaFuncSetAttribute(lista_hmma_kernel<3>,
                         cudaFuncAttributeMaxDynamicSharedMemorySize, FSMEM);

    fourier_hmma_kernel<<<dim3(NW / 128, BATCH / 128), blk, FSMEM>>>();

    dim3 gMID((MIDD + 127) / 128, BATCH / 128);   // 3 x 32
    dim3 gNF ((NF + 127) / 128, BATCH / 128);     // 17 x 32

    // m = relu(10 * feat @ template) : A=feat split, B=T^T split, K=NF
    lista_hmma_kernel<1><<<gMID, blk, FSMEM>>>(
        p_fhi, p_flo, NF, p_tthi, p_ttlo, NF, MIDD, NF,
        p_mhi, p_mlo, p_m, MIDD, nullptr, nullptr, 0.f, 0.f);

    for (int it = 0; it < 4; it++) {
        float c0 = (it == 0) ? -1.8f : -1.6f;
        float c1 = (it == 0) ?  0.0f :  0.2f;
        // xi = 1.6*(m@T^T) + c0*feat + c1*xi : A=m split, B=template split, K=MIDD
        lista_hmma_kernel<2><<<gNF, blk, FSMEM>>>(
            p_mhi, p_mlo, MIDD, p_thi, p_tlo, MIDD, NF, MIDD,
            p_xihi, p_xilo, nullptr, NF, p_fhi, p_flo, c0, c1);
        // m = relu(-8*(xi@T) + 0.2*m) : A=xi split, B=T^T split, K=NF
        lista_hmma_kernel<3><<<gMID, blk, FSMEM>>>(
            p_xihi, p_xilo, NF, p_tthi, p_ttlo, NF, MIDD, NF,
            p_mhi, p_mlo, p_m, MIDD, nullptr, nullptr, 0.f, 0.f);
    }

    // fp32 tail
    gemm64<4><<<dim3((MIDD + 63) / 64, BATCH / 64), blk>>>(
        p_m, W1, p_h1, MIDD, MIDD, MIDD, MIDD, MIDD, b1);
    gemm64<4><<<dim3((PP + 63) / 64, BATCH / 64), blk>>>(
        p_h1, W2, p_h2, PP, MIDD, MIDD, MIDD, PP, b2);
    gemm64<6><<<dim3((PP + 63) / 64, BATCH / 64), blk>>>(
        p_h2, Wout, out, PP, PP, PP, PP, PP, bout);
}

// round 6
// speedup vs baseline: 2.9243x; 1.0815x over previous
#include <cuda_runtime.h>
#include <cuda_bf16.h>
#include <math.h>
#include <stdint.h>

#define BATCH 4096
#define LEN   8192
#define NF    2112
#define MIDD  264
#define PP    88
#define NW    (2 * NF)

// ---------------------------------------------------------------------------
// Device scratch (allocation-free rule)
// ---------------------------------------------------------------------------
__device__ float g_scale2[BATCH];
__device__ float g_m  [BATCH * MIDD];
__device__ float g_h1 [BATCH * MIDD];
__device__ float g_h2 [BATCH * PP];

__device__ __align__(16) __nv_bfloat16 g_xhi[(size_t)BATCH * LEN];
__device__ __align__(16) __nv_bfloat16 g_xlo[(size_t)BATCH * LEN];
__device__ __align__(16) __nv_bfloat16 g_whi[(size_t)NW * LEN];
__device__ __align__(16) __nv_bfloat16 g_wlo[(size_t)NW * LEN];

__device__ __align__(16) __nv_bfloat16 g_fhi [(size_t)BATCH * NF];
__device__ __align__(16) __nv_bfloat16 g_flo [(size_t)BATCH * NF];
__device__ __align__(16) __nv_bfloat16 g_xihi[(size_t)BATCH * NF];
__device__ __align__(16) __nv_bfloat16 g_xilo[(size_t)BATCH * NF];
__device__ __align__(16) __nv_bfloat16 g_mhi [(size_t)BATCH * MIDD];
__device__ __align__(16) __nv_bfloat16 g_mlo [(size_t)BATCH * MIDD];
__device__ __align__(16) __nv_bfloat16 g_thi [(size_t)NF * MIDD];
__device__ __align__(16) __nv_bfloat16 g_tlo [(size_t)NF * MIDD];
__device__ __align__(16) __nv_bfloat16 g_tthi[(size_t)MIDD * NF];
__device__ __align__(16) __nv_bfloat16 g_ttlo[(size_t)MIDD * NF];

// ---------------------------------------------------------------------------
// PTX helpers
// ---------------------------------------------------------------------------
__device__ __forceinline__ uint32_t smem_u32(const void* p) {
    uint32_t a;
    asm("{ .reg .u64 t; cvta.to.shared.u64 t, %1; cvt.u32.u64 %0, t; }" : "=r"(a) : "l"(p));
    return a;
}
__device__ __forceinline__ void cp16(uint32_t saddr, const void* gaddr) {
    asm volatile("cp.async.cg.shared.global [%0], [%1], 16;" :: "r"(saddr), "l"(gaddr));
}
__device__ __forceinline__ void cp16z(uint32_t saddr, const void* gaddr, int valid) {
    asm volatile("cp.async.cg.shared.global [%0], [%1], 16, %2;"
                 :: "r"(saddr), "l"(gaddr), "r"(valid ? 16 : 0));
}
__device__ __forceinline__ void cp_commit() { asm volatile("cp.async.commit_group;"); }
__device__ __forceinline__ void cp_wait1()  { asm volatile("cp.async.wait_group 1;" ::: "memory"); }
__device__ __forceinline__ void cp_wait0()  { asm volatile("cp.async.wait_group 0;" ::: "memory"); }

__device__ __forceinline__ void ldsm4(uint32_t r[4], uint32_t a) {
    asm volatile("ldmatrix.sync.aligned.m8n8.x4.shared.b16 {%0,%1,%2,%3}, [%4];"
                 : "=r"(r[0]), "=r"(r[1]), "=r"(r[2]), "=r"(r[3]) : "r"(a));
}
__device__ __forceinline__ void mma16816(float c[4], const uint32_t a[4],
                                         uint32_t b0, uint32_t b1) {
    asm volatile(
        "mma.sync.aligned.m16n8k16.row.col.f32.bf16.bf16.f32 "
        "{%0,%1,%2,%3}, {%4,%5,%6,%7}, {%8,%9}, {%0,%1,%2,%3};"
        : "+f"(c[0]), "+f"(c[1]), "+f"(c[2]), "+f"(c[3])
        : "r"(a[0]), "r"(a[1]), "r"(a[2]), "r"(a[3]), "r"(b0), "r"(b1));
}

__device__ __forceinline__ void split_store(__nv_bfloat16* hi, __nv_bfloat16* lo,
                                            size_t idx, float v) {
    __nv_bfloat16 h = __float2bfloat16(v);
    hi[idx] = h;
    lo[idx] = __float2bfloat16(v - __bfloat162float(h));
}
__device__ __forceinline__ float split_load(const __nv_bfloat16* hi,
                                            const __nv_bfloat16* lo, size_t idx) {
    return __bfloat162float(hi[idx]) + __bfloat162float(lo[idx]);
}

__device__ __forceinline__ void split4(float4 v, uint2& hi, uint2& lo)
{
    float f[4] = {v.x, v.y, v.z, v.w};
    uint32_t hb[4], lb[4];
    #pragma unroll
    for (int j = 0; j < 4; j++) {
        __nv_bfloat16 h = __float2bfloat16(f[j]);
        float r = f[j] - __bfloat162float(h);
        __nv_bfloat16 l = __float2bfloat16(r);
        hb[j] = (uint32_t)__bfloat16_as_ushort(h);
        lb[j] = (uint32_t)__bfloat16_as_ushort(l);
    }
    hi = make_uint2(hb[0] | (hb[1] << 16), hb[2] | (hb[3] << 16));
    lo = make_uint2(lb[0] | (lb[1] << 16), lb[2] | (lb[3] << 16));
}

// ---------------------------------------------------------------------------
// fused: per-row nonzero count -> scale^2, plus X hi/lo split (one read pass)
// ---------------------------------------------------------------------------
__global__ void splitcount_x_kernel(const float* __restrict__ x)
{
    int b = blockIdx.x;
    const float4* row = (const float4*)(x + (size_t)b * LEN);
    uint2* oh = (uint2*)(g_xhi + (size_t)b * LEN);
    uint2* ol = (uint2*)(g_xlo + (size_t)b * LEN);
    int cnt = 0;
    for (int i = threadIdx.x; i < LEN / 4; i += 256) {
        float4 v = row[i];
        cnt += (v.x != 0.0f) + (v.y != 0.0f) + (v.z != 0.0f) + (v.w != 0.0f);
        uint2 h, l;
        split4(v, h, l);
        oh[i] = h;
        ol[i] = l;
    }
    #pragma unroll
    for (int o = 16; o > 0; o >>= 1) cnt += __shfl_down_sync(0xffffffffu, cnt, o);
    __shared__ int ws[8];
    if ((threadIdx.x & 31) == 0) ws[threadIdx.x >> 5] = cnt;
    __syncthreads();
    if (threadIdx.x == 0) {
        int t = 0;
        #pragma unroll
        for (int i = 0; i < 8; i++) t += ws[i];
        float s = (float)LEN / (float)(t + 1);
        g_scale2[b] = s * s;
    }
}

__global__ void split_w_kernel(const float* __restrict__ wc, const float* __restrict__ ws)
{
    int i = blockIdx.x * blockDim.x + threadIdx.x;
    if (i >= NF * (LEN / 4)) return;
    int f  = i / (LEN / 4);
    int kq = i % (LEN / 4);
    uint2 h, l;
    split4(((const float4*)wc)[i], h, l);
    size_t oc = (size_t)(2 * f) * (LEN / 4) + kq;
    ((uint2*)g_whi)[oc] = h;
    ((uint2*)g_wlo)[oc] = l;
    split4(((const float4*)ws)[i], h, l);
    size_t os = (size_t)(2 * f + 1) * (LEN / 4) + kq;
    ((uint2*)g_whi)[os] = h;
    ((uint2*)g_wlo)[os] = l;
}

__global__ void split_t_kernel(const float* __restrict__ tmpl)
{
    int i = blockIdx.x * blockDim.x + threadIdx.x;
    if (i >= NF * MIDD) return;
    int r = i / MIDD, c = i % MIDD;
    float x = tmpl[i];
    __nv_bfloat16 h = __float2bfloat16(x);
    __nv_bfloat16 l = __float2bfloat16(x - __bfloat162float(h));
    g_thi[i] = h;  g_tlo[i] = l;
    size_t ti = (size_t)c * NF + r;
    g_tthi[ti] = h;  g_ttlo[ti] = l;
}

// ---------------------------------------------------------------------------
// Fourier HMMA: CTA 128x128, KC=64, double buffer, group rasterization
// ---------------------------------------------------------------------------
#define KC       64
#define TILE_B   (128 * KC * 2)
#define STAGE_B  (4 * TILE_B)
#define FSMEM    (2 * STAGE_B)

__device__ __forceinline__ void load_chunk(uint32_t sbase, int m0, int n0, int k0, int tid)
{
    const __nv_bfloat16* srcs[4] = {
        g_xhi + (size_t)m0 * LEN, g_xlo + (size_t)m0 * LEN,
        g_whi + (size_t)n0 * LEN, g_wlo + (size_t)n0 * LEN };
    #pragma unroll
    for (int t = 0; t < 4; t++) {
        uint32_t tb = sbase + t * TILE_B;
        #pragma unroll
        for (int j = 0; j < 4; j++) {
            int c  = tid + j * 256;
            int r  = c >> 3;
            int kc = c & 7;
            const void* g = srcs[t] + (size_t)r * LEN + k0 + kc * 8;
            uint32_t s = tb + r * 128 + (((uint32_t)(kc ^ (r & 7))) << 4);
            cp16(s, g);
        }
    }
}

__global__ __launch_bounds__(256, 1) void fourier_hmma_kernel()
{
    extern __shared__ char smem_raw[];
    const uint32_t sb = smem_u32(smem_raw);

    const int tid  = threadIdx.x;
    const int wid  = tid >> 5;
    const int lane = tid & 31;
    const int wm   = wid >> 2;
    const int wn   = wid & 3;

    // group rasterization: consecutive CTAs share 8 M-tiles, walk N
    const int TM = BATCH / 128;          // 32
    const int TN = NW / 128;             // 33
    const int G  = 8;
    int lin   = blockIdx.y * gridDim.x + blockIdx.x;
    int group = lin / (G * TN);
    int rem   = lin % (G * TN);
    int mt    = group * G + (rem % G);
    int nt    = rem / G;
    (void)TM;
    const int m0 = mt * 128;
    const int n0 = nt * 128;

    float acc[4][4][4];
    #pragma unroll
    for (int i = 0; i < 4; i++)
        #pragma unroll
        for (int j = 0; j < 4; j++)
            #pragma unroll
            for (int q = 0; q < 4; q++) acc[i][j][q] = 0.0f;

    const int a_r   = lane & 15;
    const int a_k8  = lane >> 4;
    const uint32_t a_x = (uint32_t)(a_r & 7);
    const int bg    = lane >> 3;
    const int b_n   = ((bg >> 1) << 3) + (lane & 7);
    const int b_k8  = bg & 1;
    const uint32_t b_x = (uint32_t)(lane & 7);

    uint32_t a_row_b[4], b_row_b[2];
    #pragma unroll
    for (int mi = 0; mi < 4; mi++) a_row_b[mi] = (uint32_t)(wm * 64 + mi * 16 + a_r) * 128u;
    #pragma unroll
    for (int pr = 0; pr < 2; pr++) b_row_b[pr] = (uint32_t)(wn * 32 + pr * 16 + b_n) * 128u;

    const int NCH = LEN / KC;
    load_chunk(sb, m0, n0, 0, tid);
    cp_commit();

    for (int i = 0; i < NCH; i++) {
        const uint32_t su = sb + (uint32_t)(i & 1) * STAGE_B;
        if (i + 1 < NCH) {
            load_chunk(sb + (uint32_t)((i + 1) & 1) * STAGE_B, m0, n0, (i + 1) * KC, tid);
            cp_commit();
            cp_wait1();
        } else {
            cp_wait0();
        }
        __syncthreads();

        const uint32_t ah_b = su;
        const uint32_t al_b = su + TILE_B;
        const uint32_t bh_b = su + 2 * TILE_B;
        const uint32_t bl_b = su + 3 * TILE_B;

        #pragma unroll
        for (int ks = 0; ks < KC / 16; ks++) {
            const uint32_t akc = (uint32_t)(ks * 2 + a_k8);
            const uint32_t bkc = (uint32_t)(ks * 2 + b_k8);
            uint32_t ah[4][4], al[4][4];
            #pragma unroll
            for (int mi = 0; mi < 4; mi++) {
                uint32_t off = a_row_b[mi] + ((akc ^ a_x) << 4);
                ldsm4(ah[mi], ah_b + off);
                ldsm4(al[mi], al_b + off);
            }
            uint32_t bh[8], bl[8];
            #pragma unroll
            for (int pr = 0; pr < 2; pr++) {
                uint32_t off = b_row_b[pr] + ((bkc ^ b_x) << 4);
                ldsm4(&bh[pr * 4], bh_b + off);
                ldsm4(&bl[pr * 4], bl_b + off);
            }
            #pragma unroll
            for (int mi = 0; mi < 4; mi++)
                #pragma unroll
                for (int ni = 0; ni < 4; ni++) {
                    mma16816(acc[mi][ni], ah[mi], bh[ni * 2], bh[ni * 2 + 1]);
                    mma16816(acc[mi][ni], ah[mi], bl[ni * 2], bl[ni * 2 + 1]);
                    mma16816(acc[mi][ni], al[mi], bh[ni * 2], bh[ni * 2 + 1]);
                }
        }
        __syncthreads();
    }

    const int qr = lane >> 2;
    const int qc = lane & 3;
    const int fbase = (n0 >> 1) + wn * 16;
    #pragma unroll
    for (int mi = 0; mi < 4; mi++) {
        int row0 = m0 + wm * 64 + mi * 16 + qr;
        int row1 = row0 + 8;
        float s20 = g_scale2[row0];
        float s21 = g_scale2[row1];
        size_t b0 = (size_t)row0 * NF;
        size_t b1 = (size_t)row1 * NF;
        #pragma unroll
        for (int ni = 0; ni < 4; ni++) {
            int f = fbase + ni * 4 + qc;
            float c0 = acc[mi][ni][0], c1 = acc[mi][ni][1];
            float c2 = acc[mi][ni][2], c3 = acc[mi][ni][3];
            split_store(g_fhi, g_flo, b0 + f, s20 * (c0 * c0 + c1 * c1));
            split_store(g_fhi, g_flo, b1 + f, s21 * (c2 * c2 + c3 * c3));
        }
    }
}

// ---------------------------------------------------------------------------
// LISTA HMMA: CTA 128(M) x 64(N), KC=64, 2 CTAs/SM
// EPI 1: relu(10*acc) -> C split + Cf
// EPI 2: 1.6*acc + c0*X + c1*C_old -> C split
// EPI 3: relu(-8*acc + 0.2*C_old) -> C split + Cf
// ---------------------------------------------------------------------------
#define TILE_A   16384                    // 128 rows * 128B
#define TILE_Bs  8192                     // 64 rows * 128B
#define LSTAGE   (2 * TILE_A + 2 * TILE_Bs)  // 49152
#define LSMEM    (2 * LSTAGE)                // 98304

__device__ __forceinline__ void load_chunk_l(
    uint32_t sbase,
    const __nv_bfloat16* __restrict__ Ahi, const __nv_bfloat16* __restrict__ Alo,
    int lda, int m0,
    const __nv_bfloat16* __restrict__ Bhi, const __nv_bfloat16* __restrict__ Blo,
    int ldb, int n0, int N,
    int k0, int K, int tid)
{
    #pragma unroll
    for (int j = 0; j < 4; j++) {
        int c  = tid + j * 256;
        int r  = c >> 3;
        int kc = c & 7;
        int k  = k0 + kc * 8;
        int kv = (k < K);
        uint32_t soff = (uint32_t)r * 128u + (((uint32_t)(kc ^ (r & 7))) << 4);
        cp16z(sbase + soff,
              kv ? (const void*)(Ahi + (size_t)(m0 + r) * lda + k) : (const void*)Ahi, kv);
        cp16z(sbase + TILE_A + soff,
              kv ? (const void*)(Alo + (size_t)(m0 + r) * lda + k) : (const void*)Alo, kv);
    }
    #pragma unroll
    for (int j = 0; j < 2; j++) {
        int c  = tid + j * 256;
        int r  = c >> 3;                 // 0..63
        int kc = c & 7;
        int k  = k0 + kc * 8;
        int nv = (k < K) && (n0 + r < N);
        uint32_t soff = (uint32_t)r * 128u + (((uint32_t)(kc ^ (r & 7))) << 4);
        cp16z(sbase + 2 * TILE_A + soff,
              nv ? (const void*)(Bhi + (size_t)(n0 + r) * ldb + k) : (const void*)Bhi, nv);
        cp16z(sbase + 2 * TILE_A + TILE_Bs + soff,
              nv ? (const void*)(Blo + (size_t)(n0 + r) * ldb + k) : (const void*)Blo, nv);
    }
}

template<int EPI>
__global__ __launch_bounds__(256, 2) void lista_hmma_kernel(
    const __nv_bfloat16* __restrict__ Ahi, const __nv_bfloat16* __restrict__ Alo, int lda,
    const __nv_bfloat16* __restrict__ Bhi, const __nv_bfloat16* __restrict__ Blo, int ldb,
    int N, int K,
    __nv_bfloat16* __restrict__ Chi, __nv_bfloat16* __restrict__ Clo,
    float* __restrict__ Cf, int ldc,
    const __nv_bfloat16* __restrict__ Xhi, const __nv_bfloat16* __restrict__ Xlo,
    float c0, float c1)
{
    extern __shared__ char smem_raw[];
    const uint32_t sb = smem_u32(smem_raw);

    const int tid  = threadIdx.x;
    const int wid  = tid >> 5;
    const int lane = tid & 31;
    const int wm   = wid >> 1;            // 0..3
    const int wn   = wid & 1;             // 0..1
    const int m0   = blockIdx.y * 128;
    const int n0   = blockIdx.x * 64;

    float acc[2][4][4];
    #pragma unroll
    for (int i = 0; i < 2; i++)
        #pragma unroll
        for (int j = 0; j < 4; j++)
            #pragma unroll
            for (int q = 0; q < 4; q++) acc[i][j][q] = 0.0f;

    const int a_r   = lane & 15;
    const int a_k8  = lane >> 4;
    const uint32_t a_x = (uint32_t)(a_r & 7);
    const int bg    = lane >> 3;
    const int b_n   = ((bg >> 1) << 3) + (lane & 7);
    const int b_k8  = bg & 1;
    const uint32_t b_x = (uint32_t)(lane & 7);

    uint32_t a_row_b[2], b_row_b[2];
    #pragma unroll
    for (int mi = 0; mi < 2; mi++) a_row_b[mi] = (uint32_t)(wm * 32 + mi * 16 + a_r) * 128u;
    #pragma unroll
    for (int pr = 0; pr < 2; pr++) b_row_b[pr] = (uint32_t)(wn * 32 + pr * 16 + b_n) * 128u;

    const int NCH = (K + KC - 1) / KC;
    load_chunk_l(sb, Ahi, Alo, lda, m0, Bhi, Blo, ldb, n0, N, 0, K, tid);
    cp_commit();

    for (int i = 0; i < NCH; i++) {
        const uint32_t su = sb + (uint32_t)(i & 1) * LSTAGE;
        if (i + 1 < NCH) {
            load_chunk_l(sb + (uint32_t)((i + 1) & 1) * LSTAGE,
                         Ahi, Alo, lda, m0, Bhi, Blo, ldb, n0, N, (i + 1) * KC, K, tid);
            cp_commit();
            cp_wait1();
        } else {
            cp_wait0();
        }
        __syncthreads();

        const uint32_t ah_b = su;
        const uint32_t al_b = su + TILE_A;
        const uint32_t bh_b = su + 2 * TILE_A;
        const uint32_t bl_b = su + 2 * TILE_A + TILE_Bs;

        #pragma unroll
        for (int ks = 0; ks < KC / 16; ks++) {
            const uint32_t akc = (uint32_t)(ks * 2 + a_k8);
            const uint32_t bkc = (uint32_t)(ks * 2 + b_k8);
            uint32_t ah[2][4], al[2][4];
            #pragma unroll
            for (int mi = 0; mi < 2; mi++) {
                uint32_t off = a_row_b[mi] + ((akc ^ a_x) << 4);
                ldsm4(ah[mi], ah_b + off);
                ldsm4(al[mi], al_b + off);
            }
            uint32_t bh[8], bl[8];
            #pragma unroll
            for (int pr = 0; pr < 2; pr++) {
                uint32_t off = b_row_b[pr] + ((bkc ^ b_x) << 4);
                ldsm4(&bh[pr * 4], bh_b + off);
                ldsm4(&bl[pr * 4], bl_b + off);
            }
            #pragma unroll
            for (int mi = 0; mi < 2; mi++)
                #pragma unroll
                for (int ni = 0; ni < 4; ni++) {
                    mma16816(acc[mi][ni], ah[mi], bh[ni * 2], bh[ni * 2 + 1]);
                    mma16816(acc[mi][ni], ah[mi], bl[ni * 2], bl[ni * 2 + 1]);
                    mma16816(acc[mi][ni], al[mi], bh[ni * 2], bh[ni * 2 + 1]);
                }
        }
        __syncthreads();
    }

    const int qr = lane >> 2;
    const int qc = lane & 3;
    #pragma unroll
    for (int mi = 0; mi < 2; mi++) {
        int rows[2];
        rows[0] = m0 + wm * 32 + mi * 16 + qr;
        rows[1] = rows[0] + 8;
        #pragma unroll
        for (int ni = 0; ni < 4; ni++) {
            int colb = n0 + wn * 32 + ni * 8 + qc * 2;
            #pragma unroll
            for (int h = 0; h < 2; h++) {
                #pragma unroll
                for (int cc = 0; cc < 2; cc++) {
                    int col = colb + cc;
                    if (col >= N) continue;
                    size_t idx = (size_t)rows[h] * ldc + col;
                    float a = acc[mi][ni][h * 2 + cc];
                    float v;
                    if (EPI == 1) {
                        v = fmaxf(10.0f * a, 0.0f);
                    } else if (EPI == 2) {
                        v = 1.6f * a + c0 * split_load(Xhi, Xlo, idx);
                        if (c1 != 0.0f) v += c1 * split_load(Chi, Clo, idx);
                    } else {
                        float mo = split_load(Chi, Clo, idx);
                        v = fmaxf(-8.0f * a + 0.2f * mo, 0.0f);
                    }
                    split_store(Chi, Clo, idx, v);
                    if (EPI == 1 || EPI == 3) Cf[idx] = v;
                }
            }
        }
    }
}

// ---------------------------------------------------------------------------
// fp32 SIMT GEMM (tail only)
// ---------------------------------------------------------------------------
template<int EPI>
__global__ void gemm64(const float* __restrict__ A, const float* __restrict__ B0,
                       float* __restrict__ C,
                       int N, int K, int lda, int ldb, int ldc,
                       const float* __restrict__ bias)
{
    __shared__ __align__(16) float As [8][68];
    __shared__ __align__(16) float Bs0[8][68];

    const int t  = threadIdx.x;
    const int tx = t & 15;
    const int ty = t >> 4;
    const int m0 = blockIdx.y * 64;
    const int n0 = blockIdx.x * 64;

    float acc0[4][4];
    #pragma unroll
    for (int i = 0; i < 4; i++)
        #pragma unroll
        for (int j = 0; j < 4; j++) acc0[i][j] = 0.0f;

    const int arow = t >> 2;
    const int ak   = (t & 3) * 2;

    for (int k0 = 0; k0 < K; k0 += 8) {
        {
            float2 av = *(const float2*)(A + (size_t)(m0 + arow) * lda + k0 + ak);
            As[ak][arow] = av.x; As[ak + 1][arow] = av.y;
        }
        {
            int n = n0 + arow;
            float2 bv = make_float2(0.0f, 0.0f);
            if (n < N) bv = *(const float2*)(B0 + (size_t)n * ldb + k0 + ak);
            Bs0[ak][arow] = bv.x; Bs0[ak + 1][arow] = bv.y;
        }
        __syncthreads();

        #pragma unroll
        for (int kk = 0; kk < 8; kk++) {
            float4 a = *(const float4*)&As [kk][ty * 4];
            float4 b = *(const float4*)&Bs0[kk][tx * 4];
            float av4[4] = {a.x, a.y, a.z, a.w};
            float bv4[4] = {b.x, b.y, b.z, b.w};
            #pragma unroll
            for (int i = 0; i < 4; i++)
                #pragma unroll
                for (int j = 0; j < 4; j++)
                    acc0[i][j] += av4[i] * bv4[j];
        }
        __syncthreads();
    }

    #pragma unroll
    for (int i = 0; i < 4; i++) {
        int row = m0 + ty * 4 + i;
        #pragma unroll
        for (int j = 0; j < 4; j++) {
            int col = n0 + tx * 4 + j;
            if (col >= N) continue;
            size_t idx = (size_t)row * ldc + col;
            float v;
            if (EPI == 4) {
                v = fmaxf(acc0[i][j] + bias[col], 0.0f);
            } else {
                float z = acc0[i][j] + bias[col];
                v = 1.0f / (1.0f + expf(-z));
            }
            C[idx] = v;
        }
    }
}

// ---------------------------------------------------------------------------
extern "C" void kernel_launch(void* const* d_in, const int* in_sizes, int n_in,
                              void* d_out, int out_size)
{
    const float* input_this = (const float*)d_in[0];
    const float* W_cos = (const float*)d_in[2];
    const float* W_sin = (const float*)d_in[3];
    const float* tmpl  = (const float*)d_in[4];
    const float* W1    = (const float*)d_in[5];
    const float* b1    = (const float*)d_in[6];
    const float* W2    = (const float*)d_in[7];
    const float* b2    = (const float*)d_in[8];
    const float* Wout  = (const float*)d_in[9];
    const float* bout  = (const float*)d_in[10];
    float* out = (float*)d_out;

    float *p_m, *p_h1, *p_h2;
    cudaGetSymbolAddress((void**)&p_m,  g_m);
    cudaGetSymbolAddress((void**)&p_h1, g_h1);
    cudaGetSymbolAddress((void**)&p_h2, g_h2);
    __nv_bfloat16 *p_fhi, *p_flo, *p_xihi, *p_xilo, *p_mhi, *p_mlo;
    __nv_bfloat16 *p_thi, *p_tlo, *p_tthi, *p_ttlo;
    cudaGetSymbolAddress((void**)&p_fhi,  g_fhi);
    cudaGetSymbolAddress((void**)&p_flo,  g_flo);
    cudaGetSymbolAddress((void**)&p_xihi, g_xihi);
    cudaGetSymbolAddress((void**)&p_xilo, g_xilo);
    cudaGetSymbolAddress((void**)&p_mhi,  g_mhi);
    cudaGetSymbolAddress((void**)&p_mlo,  g_mlo);
    cudaGetSymbolAddress((void**)&p_thi,  g_thi);
    cudaGetSymbolAddress((void**)&p_tlo,  g_tlo);
    cudaGetSymbolAddress((void**)&p_tthi, g_tthi);
    cudaGetSymbolAddress((void**)&p_ttlo, g_ttlo);

    dim3 blk(256);

    splitcount_x_kernel<<<BATCH, blk>>>(input_this);
    split_w_kernel<<<(NF * LEN / 4 + 255) / 256, blk>>>(W_cos, W_sin);
    split_t_kernel<<<(NF * MIDD + 255) / 256, blk>>>(tmpl);

    cudaFuncSetAttribute(fourier_hmma_kernel,
                         cudaFuncAttributeMaxDynamicSharedMemorySize, FSMEM);
    cudaFuncSetAttribute(lista_hmma_kernel<1>,
                         cudaFuncAttributeMaxDynamicSharedMemorySize, LSMEM);
    cudaFuncSetAttribute(lista_hmma_kernel<2>,
                         cudaFuncAttributeMaxDynamicSharedMemorySize, LSMEM);
    cudaFuncSetAttribute(lista_hmma_kernel<3>,
                         cudaFuncAttributeMaxDynamicSharedMemorySize, LSMEM);

    fourier_hmma_kernel<<<dim3(NW / 128, BATCH / 128), blk, FSMEM>>>();

    dim3 gMID((MIDD + 63) / 64, BATCH / 128);   // 5 x 32 = 160 CTAs
    dim3 gNF ((NF + 63) / 64, BATCH / 128);     // 33 x 32 = 1056 CTAs

    // m = relu(10 * feat @ template)
    lista_hmma_kernel<1><<<gMID, blk, LSMEM>>>(
        p_fhi, p_flo, NF, p_tthi, p_ttlo, NF, MIDD, NF,
        p_mhi, p_mlo, p_m, MIDD, nullptr, nullptr, 0.f, 0.f);

    for (int it = 0; it < 4; it++) {
        float c0 = (it == 0) ? -1.8f : -1.6f;
        float c1 = (it == 0) ?  0.0f :  0.2f;
        lista_hmma_kernel<2><<<gNF, blk, LSMEM>>>(
            p_mhi, p_mlo, MIDD, p_thi, p_tlo, MIDD, NF, MIDD,
            p_xihi, p_xilo, nullptr, NF, p_fhi, p_flo, c0, c1);
        lista_hmma_kernel<3><<<gMID, blk, LSMEM>>>(
            p_xihi, p_xilo, NF, p_tthi, p_ttlo, NF, MIDD, NF,
            p_mhi, p_mlo, p_m, MIDD, nullptr, nullptr, 0.f, 0.f);
    }

    // fp32 tail
    gemm64<4><<<dim3((MIDD + 63) / 64, BATCH / 64), blk>>>(
        p_m, W1, p_h1, MIDD, MIDD, MIDD, MIDD, MIDD, b1);
    gemm64<4><<<dim3((PP + 63) / 64, BATCH / 64), blk>>>(
        p_h1, W2, p_h2, PP, MIDD, MIDD, MIDD, PP, b2);
    gemm64<6><<<dim3((PP + 63) / 64, BATCH / 64), blk>>>(
        p_h2, Wout, out, PP, PP, PP, PP, PP, bout);
}

// round 7
// speedup vs baseline: 3.9688x; 1.3572x over previous
#include <cuda_runtime.h>
#include <cuda_fp16.h>
#include <math.h>
#include <stdint.h>

#define BATCH 4096
#define LEN   8192
#define NF    2112
#define MIDD  264
#define PP    88
#define NW    (2 * NF)

#define WSCALE    8192.0f      // W pre-scale (2^13)
#define ALPHA_INV (1.0f / 8192.0f)
#define TSCALE    64.0f        // template pre-scale
// LISTA epilogue constants (absorb alpha=2^13, beta=64)
#define C_M0   (10.0f / 64.0f)
#define C_XI   (1.6f / 64.0f)
#define C_MUPD (-8.0f / 64.0f)

// ---------------------------------------------------------------------------
// Device scratch
// ---------------------------------------------------------------------------
__device__ float g_scale2[BATCH];      // (LEN/n)^2 * 2^-13
__device__ float g_m  [BATCH * MIDD];  // de-scaled fp32 m for tail
__device__ float g_h1 [BATCH * MIDD];
__device__ float g_h2 [BATCH * PP];

__device__ __align__(16) __half g_xhi[(size_t)BATCH * LEN];
__device__ __align__(16) __half g_xlo[(size_t)BATCH * LEN];
__device__ __align__(16) __half g_whi[(size_t)NW * LEN];      // W*2^13, hi only

__device__ __align__(16) __half g_fhi [(size_t)BATCH * NF];   // feat' = 2^13*feat
__device__ __align__(16) __half g_flo [(size_t)BATCH * NF];
__device__ __align__(16) __half g_xihi[(size_t)BATCH * NF];
__device__ __align__(16) __half g_xilo[(size_t)BATCH * NF];
__device__ __align__(16) __half g_mhi [(size_t)BATCH * MIDD];
__device__ __align__(16) __half g_mlo [(size_t)BATCH * MIDD];
__device__ __align__(16) __half g_thi [(size_t)NF * MIDD];    // T*64, hi only
__device__ __align__(16) __half g_tthi[(size_t)MIDD * NF];    // T^T*64, hi only

// ---------------------------------------------------------------------------
// PTX helpers
// ---------------------------------------------------------------------------
__device__ __forceinline__ uint32_t smem_u32(const void* p) {
    uint32_t a;
    asm("{ .reg .u64 t; cvta.to.shared.u64 t, %1; cvt.u32.u64 %0, t; }" : "=r"(a) : "l"(p));
    return a;
}
__device__ __forceinline__ void cp16(uint32_t saddr, const void* gaddr) {
    asm volatile("cp.async.cg.shared.global [%0], [%1], 16;" :: "r"(saddr), "l"(gaddr));
}
__device__ __forceinline__ void cp16z(uint32_t saddr, const void* gaddr, int valid) {
    asm volatile("cp.async.cg.shared.global [%0], [%1], 16, %2;"
                 :: "r"(saddr), "l"(gaddr), "r"(valid ? 16 : 0));
}
__device__ __forceinline__ void cp_commit() { asm volatile("cp.async.commit_group;"); }
__device__ __forceinline__ void cp_wait1()  { asm volatile("cp.async.wait_group 1;" ::: "memory"); }
__device__ __forceinline__ void cp_wait0()  { asm volatile("cp.async.wait_group 0;" ::: "memory"); }

__device__ __forceinline__ void ldsm4(uint32_t r[4], uint32_t a) {
    asm volatile("ldmatrix.sync.aligned.m8n8.x4.shared.b16 {%0,%1,%2,%3}, [%4];"
                 : "=r"(r[0]), "=r"(r[1]), "=r"(r[2]), "=r"(r[3]) : "r"(a));
}
__device__ __forceinline__ void mma16816(float c[4], const uint32_t a[4],
                                         uint32_t b0, uint32_t b1) {
    asm volatile(
        "mma.sync.aligned.m16n8k16.row.col.f32.f16.f16.f32 "
        "{%0,%1,%2,%3}, {%4,%5,%6,%7}, {%8,%9}, {%0,%1,%2,%3};"
        : "+f"(c[0]), "+f"(c[1]), "+f"(c[2]), "+f"(c[3])
        : "r"(a[0]), "r"(a[1]), "r"(a[2]), "r"(a[3]), "r"(b0), "r"(b1));
}

__device__ __forceinline__ void hsplit_store(__half* hi, __half* lo, size_t idx, float v) {
    __half h = __float2half_rn(v);
    hi[idx] = h;
    lo[idx] = __float2half_rn(v - __half2float(h));
}
__device__ __forceinline__ float hsplit_load(const __half* hi, const __half* lo, size_t idx) {
    return __half2float(hi[idx]) + __half2float(lo[idx]);
}

__device__ __forceinline__ void split4h(float4 v, uint2& hi, uint2& lo)
{
    float f[4] = {v.x, v.y, v.z, v.w};
    uint32_t hb[4], lb[4];
    #pragma unroll
    for (int j = 0; j < 4; j++) {
        __half h = __float2half_rn(f[j]);
        __half l = __float2half_rn(f[j] - __half2float(h));
        hb[j] = (uint32_t)__half_as_ushort(h);
        lb[j] = (uint32_t)__half_as_ushort(l);
    }
    hi = make_uint2(hb[0] | (hb[1] << 16), hb[2] | (hb[3] << 16));
    lo = make_uint2(lb[0] | (lb[1] << 16), lb[2] | (lb[3] << 16));
}
__device__ __forceinline__ uint2 pack4h(float4 v)
{
    uint32_t hb[4];
    float f[4] = {v.x, v.y, v.z, v.w};
    #pragma unroll
    for (int j = 0; j < 4; j++)
        hb[j] = (uint32_t)__half_as_ushort(__float2half_rn(f[j]));
    return make_uint2(hb[0] | (hb[1] << 16), hb[2] | (hb[3] << 16));
}

// ---------------------------------------------------------------------------
// fused: count -> scale^2 (with 2^-13) + X fp16 hi/lo split
// ---------------------------------------------------------------------------
__global__ void splitcount_x_kernel(const float* __restrict__ x)
{
    int b = blockIdx.x;
    const float4* row = (const float4*)(x + (size_t)b * LEN);
    uint2* oh = (uint2*)(g_xhi + (size_t)b * LEN);
    uint2* ol = (uint2*)(g_xlo + (size_t)b * LEN);
    int cnt = 0;
    for (int i = threadIdx.x; i < LEN / 4; i += 256) {
        float4 v = row[i];
        cnt += (v.x != 0.0f) + (v.y != 0.0f) + (v.z != 0.0f) + (v.w != 0.0f);
        uint2 h, l;
        split4h(v, h, l);
        oh[i] = h;
        ol[i] = l;
    }
    #pragma unroll
    for (int o = 16; o > 0; o >>= 1) cnt += __shfl_down_sync(0xffffffffu, cnt, o);
    __shared__ int ws[8];
    if ((threadIdx.x & 31) == 0) ws[threadIdx.x >> 5] = cnt;
    __syncthreads();
    if (threadIdx.x == 0) {
        int t = 0;
        #pragma unroll
        for (int i = 0; i < 8; i++) t += ws[i];
        float s = (float)LEN / (float)(t + 1);
        g_scale2[b] = s * s * ALPHA_INV;
    }
}

// W interleaved cos/sin, scaled by 2^13, fp16 hi only
__global__ void split_w_kernel(const float* __restrict__ wc, const float* __restrict__ ws)
{
    int i = blockIdx.x * blockDim.x + threadIdx.x;
    if (i >= NF * (LEN / 4)) return;
    int f  = i / (LEN / 4);
    int kq = i % (LEN / 4);
    float4 vc = ((const float4*)wc)[i];
    vc.x *= WSCALE; vc.y *= WSCALE; vc.z *= WSCALE; vc.w *= WSCALE;
    ((uint2*)g_whi)[(size_t)(2 * f) * (LEN / 4) + kq] = pack4h(vc);
    float4 vs = ((const float4*)ws)[i];
    vs.x *= WSCALE; vs.y *= WSCALE; vs.z *= WSCALE; vs.w *= WSCALE;
    ((uint2*)g_whi)[(size_t)(2 * f + 1) * (LEN / 4) + kq] = pack4h(vs);
}

// template*64, fp16 hi only, plus transpose
__global__ void split_t_kernel(const float* __restrict__ tmpl)
{
    int i = blockIdx.x * blockDim.x + threadIdx.x;
    if (i >= NF * MIDD) return;
    int r = i / MIDD, c = i % MIDD;
    __half h = __float2half_rn(tmpl[i] * TSCALE);
    g_thi[i] = h;
    g_tthi[(size_t)c * NF + r] = h;
}

// ---------------------------------------------------------------------------
// Fourier HMMA: CTA 128x128, KC=64, 2-pass fp16 (hi*hi + lo*hi)
// ---------------------------------------------------------------------------
#define KC       64
#define TILE_T   (128 * KC * 2)          // 16384 bytes
#define STAGE_F  (3 * TILE_T)            // Ahi, Alo, Bhi
#define FSMEM    (2 * STAGE_F)           // 98304

__device__ __forceinline__ void load_chunk(uint32_t sbase, int m0, int n0, int k0, int tid)
{
    const __half* srcs[3] = {
        g_xhi + (size_t)m0 * LEN, g_xlo + (size_t)m0 * LEN,
        g_whi + (size_t)n0 * LEN };
    #pragma unroll
    for (int t = 0; t < 3; t++) {
        uint32_t tb = sbase + t * TILE_T;
        #pragma unroll
        for (int j = 0; j < 4; j++) {
            int c  = tid + j * 256;
            int r  = c >> 3;
            int kc = c & 7;
            const void* g = srcs[t] + (size_t)r * LEN + k0 + kc * 8;
            uint32_t s = tb + r * 128 + (((uint32_t)(kc ^ (r & 7))) << 4);
            cp16(s, g);
        }
    }
}

__global__ __launch_bounds__(256, 1) void fourier_hmma_kernel()
{
    extern __shared__ char smem_raw[];
    const uint32_t sb = smem_u32(smem_raw);

    const int tid  = threadIdx.x;
    const int wid  = tid >> 5;
    const int lane = tid & 31;
    const int wm   = wid >> 2;
    const int wn   = wid & 3;

    const int TN = NW / 128;             // 33
    const int G  = 8;
    int lin   = blockIdx.y * gridDim.x + blockIdx.x;
    int group = lin / (G * TN);
    int rem   = lin % (G * TN);
    int mt    = group * G + (rem % G);
    int nt    = rem / G;
    const int m0 = mt * 128;
    const int n0 = nt * 128;

    float acc[4][4][4];
    #pragma unroll
    for (int i = 0; i < 4; i++)
        #pragma unroll
        for (int j = 0; j < 4; j++)
            #pragma unroll
            for (int q = 0; q < 4; q++) acc[i][j][q] = 0.0f;

    const int a_r   = lane & 15;
    const int a_k8  = lane >> 4;
    const uint32_t a_x = (uint32_t)(a_r & 7);
    const int bg    = lane >> 3;
    const int b_n   = ((bg >> 1) << 3) + (lane & 7);
    const int b_k8  = bg & 1;
    const uint32_t b_x = (uint32_t)(lane & 7);

    uint32_t a_row_b[4], b_row_b[2];
    #pragma unroll
    for (int mi = 0; mi < 4; mi++) a_row_b[mi] = (uint32_t)(wm * 64 + mi * 16 + a_r) * 128u;
    #pragma unroll
    for (int pr = 0; pr < 2; pr++) b_row_b[pr] = (uint32_t)(wn * 32 + pr * 16 + b_n) * 128u;

    const int NCH = LEN / KC;
    load_chunk(sb, m0, n0, 0, tid);
    cp_commit();

    for (int i = 0; i < NCH; i++) {
        const uint32_t su = sb + (uint32_t)(i & 1) * STAGE_F;
        if (i + 1 < NCH) {
            load_chunk(sb + (uint32_t)((i + 1) & 1) * STAGE_F, m0, n0, (i + 1) * KC, tid);
            cp_commit();
            cp_wait1();
        } else {
            cp_wait0();
        }
        __syncthreads();

        const uint32_t ah_b = su;
        const uint32_t al_b = su + TILE_T;
        const uint32_t bh_b = su + 2 * TILE_T;

        #pragma unroll
        for (int ks = 0; ks < KC / 16; ks++) {
            const uint32_t akc = (uint32_t)(ks * 2 + a_k8);
            const uint32_t bkc = (uint32_t)(ks * 2 + b_k8);
            uint32_t ah[4][4], al[4][4];
            #pragma unroll
            for (int mi = 0; mi < 4; mi++) {
                uint32_t off = a_row_b[mi] + ((akc ^ a_x) << 4);
                ldsm4(ah[mi], ah_b + off);
                ldsm4(al[mi], al_b + off);
            }
            uint32_t bh[8];
            #pragma unroll
            for (int pr = 0; pr < 2; pr++) {
                uint32_t off = b_row_b[pr] + ((bkc ^ b_x) << 4);
                ldsm4(&bh[pr * 4], bh_b + off);
            }
            #pragma unroll
            for (int mi = 0; mi < 4; mi++)
                #pragma unroll
                for (int ni = 0; ni < 4; ni++) {
                    mma16816(acc[mi][ni], ah[mi], bh[ni * 2], bh[ni * 2 + 1]);
                    mma16816(acc[mi][ni], al[mi], bh[ni * 2], bh[ni * 2 + 1]);
                }
        }
        __syncthreads();
    }

    // epilogue: feat' = s2 * (c^2 + s^2)  (s2 already has 2^-13)
    const int qr = lane >> 2;
    const int qc = lane & 3;
    const int fbase = (n0 >> 1) + wn * 16;
    #pragma unroll
    for (int mi = 0; mi < 4; mi++) {
        int row0 = m0 + wm * 64 + mi * 16 + qr;
        int row1 = row0 + 8;
        float s20 = g_scale2[row0];
        float s21 = g_scale2[row1];
        size_t b0 = (size_t)row0 * NF;
        size_t b1 = (size_t)row1 * NF;
        #pragma unroll
        for (int ni = 0; ni < 4; ni++) {
            int f = fbase + ni * 4 + qc;
            float c0 = acc[mi][ni][0], c1 = acc[mi][ni][1];
            float c2 = acc[mi][ni][2], c3 = acc[mi][ni][3];
            hsplit_store(g_fhi, g_flo, b0 + f, s20 * (c0 * c0 + c1 * c1));
            hsplit_store(g_fhi, g_flo, b1 + f, s21 * (c2 * c2 + c3 * c3));
        }
    }
}

// ---------------------------------------------------------------------------
// LISTA HMMA: CTA 128x64, KC=64, 2-pass fp16, B hi-only
// EPI 1: m' = relu(C_M0*acc);   Cf = m'*2^-13
// EPI 2: xi' = C_XI*acc + c0*feat' + c1*xi'_old
// EPI 3: m' = relu(C_MUPD*acc + 0.2*m'_old);  Cf = m'*2^-13
// ---------------------------------------------------------------------------
#define TILE_A   16384
#define TILE_Bs  8192
#define LSTAGE   (2 * TILE_A + TILE_Bs)   // 40960
#define LSMEM    (2 * LSTAGE)             // 81920

__device__ __forceinline__ void load_chunk_l(
    uint32_t sbase,
    const __half* __restrict__ Ahi, const __half* __restrict__ Alo, int lda, int m0,
    const __half* __restrict__ Bhi, int ldb, int n0, int N,
    int k0, int K, int tid)
{
    #pragma unroll
    for (int j = 0; j < 4; j++) {
        int c  = tid + j * 256;
        int r  = c >> 3;
        int kc = c & 7;
        int k  = k0 + kc * 8;
        int kv = (k < K);
        uint32_t soff = (uint32_t)r * 128u + (((uint32_t)(kc ^ (r & 7))) << 4);
        cp16z(sbase + soff,
              kv ? (const void*)(Ahi + (size_t)(m0 + r) * lda + k) : (const void*)Ahi, kv);
        cp16z(sbase + TILE_A + soff,
              kv ? (const void*)(Alo + (size_t)(m0 + r) * lda + k) : (const void*)Alo, kv);
    }
    #pragma unroll
    for (int j = 0; j < 2; j++) {
        int c  = tid + j * 256;
        int r  = c >> 3;
        int kc = c & 7;
        int k  = k0 + kc * 8;
        int nv = (k < K) && (n0 + r < N);
        uint32_t soff = (uint32_t)r * 128u + (((uint32_t)(kc ^ (r & 7))) << 4);
        cp16z(sbase + 2 * TILE_A + soff,
              nv ? (const void*)(Bhi + (size_t)(n0 + r) * ldb + k) : (const void*)Bhi, nv);
    }
}

template<int EPI>
__global__ __launch_bounds__(256, 2) void lista_hmma_kernel(
    const __half* __restrict__ Ahi, const __half* __restrict__ Alo, int lda,
    const __half* __restrict__ Bhi, int ldb,
    int N, int K,
    __half* __restrict__ Chi, __half* __restrict__ Clo,
    float* __restrict__ Cf, int ldc,
    const __half* __restrict__ Xhi, const __half* __restrict__ Xlo,
    float c0, float c1)
{
    extern __shared__ char smem_raw[];
    const uint32_t sb = smem_u32(smem_raw);

    const int tid  = threadIdx.x;
    const int wid  = tid >> 5;
    const int lane = tid & 31;
    const int wm   = wid >> 1;
    const int wn   = wid & 1;
    const int m0   = blockIdx.y * 128;
    const int n0   = blockIdx.x * 64;

    float acc[2][4][4];
    #pragma unroll
    for (int i = 0; i < 2; i++)
        #pragma unroll
        for (int j = 0; j < 4; j++)
            #pragma unroll
            for (int q = 0; q < 4; q++) acc[i][j][q] = 0.0f;

    const int a_r   = lane & 15;
    const int a_k8  = lane >> 4;
    const uint32_t a_x = (uint32_t)(a_r & 7);
    const int bg    = lane >> 3;
    const int b_n   = ((bg >> 1) << 3) + (lane & 7);
    const int b_k8  = bg & 1;
    const uint32_t b_x = (uint32_t)(lane & 7);

    uint32_t a_row_b[2], b_row_b[2];
    #pragma unroll
    for (int mi = 0; mi < 2; mi++) a_row_b[mi] = (uint32_t)(wm * 32 + mi * 16 + a_r) * 128u;
    #pragma unroll
    for (int pr = 0; pr < 2; pr++) b_row_b[pr] = (uint32_t)(wn * 32 + pr * 16 + b_n) * 128u;

    const int NCH = (K + KC - 1) / KC;
    load_chunk_l(sb, Ahi, Alo, lda, m0, Bhi, ldb, n0, N, 0, K, tid);
    cp_commit();

    for (int i = 0; i < NCH; i++) {
        const uint32_t su = sb + (uint32_t)(i & 1) * LSTAGE;
        if (i + 1 < NCH) {
            load_chunk_l(sb + (uint32_t)((i + 1) & 1) * LSTAGE,
                         Ahi, Alo, lda, m0, Bhi, ldb, n0, N, (i + 1) * KC, K, tid);
            cp_commit();
            cp_wait1();
        } else {
            cp_wait0();
        }
        __syncthreads();

        const uint32_t ah_b = su;
        const uint32_t al_b = su + TILE_A;
        const uint32_t bh_b = su + 2 * TILE_A;

        #pragma unroll
        for (int ks = 0; ks < KC / 16; ks++) {
            const uint32_t akc = (uint32_t)(ks * 2 + a_k8);
            const uint32_t bkc = (uint32_t)(ks * 2 + b_k8);
            uint32_t ah[2][4], al[2][4];
            #pragma unroll
            for (int mi = 0; mi < 2; mi++) {
                uint32_t off = a_row_b[mi] + ((akc ^ a_x) << 4);
                ldsm4(ah[mi], ah_b + off);
                ldsm4(al[mi], al_b + off);
            }
            uint32_t bh[8];
            #pragma unroll
            for (int pr = 0; pr < 2; pr++) {
                uint32_t off = b_row_b[pr] + ((bkc ^ b_x) << 4);
                ldsm4(&bh[pr * 4], bh_b + off);
            }
            #pragma unroll
            for (int mi = 0; mi < 2; mi++)
                #pragma unroll
                for (int ni = 0; ni < 4; ni++) {
                    mma16816(acc[mi][ni], ah[mi], bh[ni * 2], bh[ni * 2 + 1]);
                    mma16816(acc[mi][ni], al[mi], bh[ni * 2], bh[ni * 2 + 1]);
                }
        }
        __syncthreads();
    }

    const int qr = lane >> 2;
    const int qc = lane & 3;
    #pragma unroll
    for (int mi = 0; mi < 2; mi++) {
        int rows[2];
        rows[0] = m0 + wm * 32 + mi * 16 + qr;
        rows[1] = rows[0] + 8;
        #pragma unroll
        for (int ni = 0; ni < 4; ni++) {
            int colb = n0 + wn * 32 + ni * 8 + qc * 2;
            #pragma unroll
            for (int h = 0; h < 2; h++) {
                #pragma unroll
                for (int cc = 0; cc < 2; cc++) {
                    int col = colb + cc;
                    if (col >= N) continue;
                    size_t idx = (size_t)rows[h] * ldc + col;
                    float a = acc[mi][ni][h * 2 + cc];
                    float v;
                    if (EPI == 1) {
                        v = fmaxf(C_M0 * a, 0.0f);
                    } else if (EPI == 2) {
                        v = C_XI * a + c0 * hsplit_load(Xhi, Xlo, idx);
                        if (c1 != 0.0f) v += c1 * hsplit_load(Chi, Clo, idx);
                    } else {
                        float mo = hsplit_load(Chi, Clo, idx);
                        v = fmaxf(C_MUPD * a + 0.2f * mo, 0.0f);
                    }
                    hsplit_store(Chi, Clo, idx, v);
                    if (EPI == 1 || EPI == 3) Cf[idx] = v * ALPHA_INV;
                }
            }
        }
    }
}

// ---------------------------------------------------------------------------
// fp32 SIMT GEMM (tail only)
// ---------------------------------------------------------------------------
template<int EPI>
__global__ void gemm64(const float* __restrict__ A, const float* __restrict__ B0,
                       float* __restrict__ C,
                       int N, int K, int lda, int ldb, int ldc,
                       const float* __restrict__ bias)
{
    __shared__ __align__(16) float As [8][68];
    __shared__ __align__(16) float Bs0[8][68];

    const int t  = threadIdx.x;
    const int tx = t & 15;
    const int ty = t >> 4;
    const int m0 = blockIdx.y * 64;
    const int n0 = blockIdx.x * 64;

    float acc0[4][4];
    #pragma unroll
    for (int i = 0; i < 4; i++)
        #pragma unroll
        for (int j = 0; j < 4; j++) acc0[i][j] = 0.0f;

    const int arow = t >> 2;
    const int ak   = (t & 3) * 2;

    for (int k0 = 0; k0 < K; k0 += 8) {
        {
            float2 av = *(const float2*)(A + (size_t)(m0 + arow) * lda + k0 + ak);
            As[ak][arow] = av.x; As[ak + 1][arow] = av.y;
        }
        {
            int n = n0 + arow;
            float2 bv = make_float2(0.0f, 0.0f);
            if (n < N) bv = *(const float2*)(B0 + (size_t)n * ldb + k0 + ak);
            Bs0[ak][arow] = bv.x; Bs0[ak + 1][arow] = bv.y;
        }
        __syncthreads();

        #pragma unroll
        for (int kk = 0; kk < 8; kk++) {
            float4 a = *(const float4*)&As [kk][ty * 4];
            float4 b = *(const float4*)&Bs0[kk][tx * 4];
            float av4[4] = {a.x, a.y, a.z, a.w};
            float bv4[4] = {b.x, b.y, b.z, b.w};
            #pragma unroll
            for (int i = 0; i < 4; i++)
                #pragma unroll
                for (int j = 0; j < 4; j++)
                    acc0[i][j] += av4[i] * bv4[j];
        }
        __syncthreads();
    }

    #pragma unroll
    for (int i = 0; i < 4; i++) {
        int row = m0 + ty * 4 + i;
        #pragma unroll
        for (int j = 0; j < 4; j++) {
            int col = n0 + tx * 4 + j;
            if (col >= N) continue;
            size_t idx = (size_t)row * ldc + col;
            float v;
            if (EPI == 4) {
                v = fmaxf(acc0[i][j] + bias[col], 0.0f);
            } else {
                float z = acc0[i][j] + bias[col];
                v = 1.0f / (1.0f + expf(-z));
            }
            C[idx] = v;
        }
    }
}

// ---------------------------------------------------------------------------
extern "C" void kernel_launch(void* const* d_in, const int* in_sizes, int n_in,
                              void* d_out, int out_size)
{
    const float* input_this = (const float*)d_in[0];
    const float* W_cos = (const float*)d_in[2];
    const float* W_sin = (const float*)d_in[3];
    const float* tmpl  = (const float*)d_in[4];
    const float* W1    = (const float*)d_in[5];
    const float* b1    = (const float*)d_in[6];
    const float* W2    = (const float*)d_in[7];
    const float* b2    = (const float*)d_in[8];
    const float* Wout  = (const float*)d_in[9];
    const float* bout  = (const float*)d_in[10];
    float* out = (float*)d_out;

    float *p_m, *p_h1, *p_h2;
    cudaGetSymbolAddress((void**)&p_m,  g_m);
    cudaGetSymbolAddress((void**)&p_h1, g_h1);
    cudaGetSymbolAddress((void**)&p_h2, g_h2);
    __half *p_fhi, *p_flo, *p_xihi, *p_xilo, *p_mhi, *p_mlo, *p_thi, *p_tthi;
    cudaGetSymbolAddress((void**)&p_fhi,  g_fhi);
    cudaGetSymbolAddress((void**)&p_flo,  g_flo);
    cudaGetSymbolAddress((void**)&p_xihi, g_xihi);
    cudaGetSymbolAddress((void**)&p_xilo, g_xilo);
    cudaGetSymbolAddress((void**)&p_mhi,  g_mhi);
    cudaGetSymbolAddress((void**)&p_mlo,  g_mlo);
    cudaGetSymbolAddress((void**)&p_thi,  g_thi);
    cudaGetSymbolAddress((void**)&p_tthi, g_tthi);

    dim3 blk(256);

    splitcount_x_kernel<<<BATCH, blk>>>(input_this);
    split_w_kernel<<<(NF * LEN / 4 + 255) / 256, blk>>>(W_cos, W_sin);
    split_t_kernel<<<(NF * MIDD + 255) / 256, blk>>>(tmpl);

    cudaFuncSetAttribute(fourier_hmma_kernel,
                         cudaFuncAttributeMaxDynamicSharedMemorySize, FSMEM);
    cudaFuncSetAttribute(lista_hmma_kernel<1>,
                         cudaFuncAttributeMaxDynamicSharedMemorySize, LSMEM);
    cudaFuncSetAttribute(lista_hmma_kernel<2>,
                         cudaFuncAttributeMaxDynamicSharedMemorySize, LSMEM);
    cudaFuncSetAttribute(lista_hmma_kernel<3>,
                         cudaFuncAttributeMaxDynamicSharedMemorySize, LSMEM);

    fourier_hmma_kernel<<<dim3(NW / 128, BATCH / 128), blk, FSMEM>>>();

    dim3 gMID((MIDD + 63) / 64, BATCH / 128);
    dim3 gNF ((NF + 63) / 64, BATCH / 128);

    // m' = relu(C_M0 * feat' @ T'^T)
    lista_hmma_kernel<1><<<gMID, blk, LSMEM>>>(
        p_fhi, p_flo, NF, p_tthi, NF, MIDD, NF,
        p_mhi, p_mlo, p_m, MIDD, nullptr, nullptr, 0.f, 0.f);

    for (int it = 0; it < 4; it++) {
        float c0 = (it == 0) ? -1.8f : -1.6f;
        float c1 = (it == 0) ?  0.0f :  0.2f;
        lista_hmma_kernel<2><<<gNF, blk, LSMEM>>>(
            p_mhi, p_mlo, MIDD, p_thi, MIDD, NF, MIDD,
            p_xihi, p_xilo, nullptr, NF, p_fhi, p_flo, c0, c1);
        lista_hmma_kernel<3><<<gMID, blk, LSMEM>>>(
            p_xihi, p_xilo, NF, p_tthi, NF, MIDD, NF,
            p_mhi, p_mlo, p_m, MIDD, nullptr, nullptr, 0.f, 0.f);
    }

    // fp32 tail
    gemm64<4><<<dim3((MIDD + 63) / 64, BATCH / 64), blk>>>(
        p_m, W1, p_h1, MIDD, MIDD, MIDD, MIDD, MIDD, b1);
    gemm64<4><<<dim3((PP + 63) / 64, BATCH / 64), blk>>>(
        p_h1, W2, p_h2, PP, MIDD, MIDD, MIDD, PP, b2);
    gemm64<6><<<dim3((PP + 63) / 64, BATCH / 64), blk>>>(
        p_h2, Wout, out, PP, PP, PP, PP, PP, bout);
}

// round 9
// speedup vs baseline: 6.5544x; 1.6515x over previous
#include <cuda_runtime.h>
#include <cuda_fp16.h>
#include <math.h>
#include <stdint.h>

#define BATCH 4096
#define LEN   8192
#define NF    2112
#define MIDD  264
#define PP    88
#define NW    (2 * NF)

#define WSCALE    8192.0f      // W pre-scale (2^13)
#define ALPHA_INV (1.0f / 8192.0f)
#define TSCALE    64.0f        // template pre-scale
#define C_M0   (10.0f / 64.0f)
#define C_XI   (1.6f / 64.0f)
#define C_MUPD (-8.0f / 64.0f)

// ---------------------------------------------------------------------------
// Device scratch
// ---------------------------------------------------------------------------
__device__ float g_scale2[BATCH];      // (LEN/n)^2 * 2^-13
__device__ float g_m  [BATCH * MIDD];
__device__ float g_h1 [BATCH * MIDD];
__device__ float g_h2 [BATCH * PP];

__device__ __align__(16) __half g_xhi[(size_t)BATCH * LEN];
__device__ __align__(16) __half g_whi[(size_t)NW * LEN];      // W*2^13

__device__ __align__(16) __half g_fhi [(size_t)BATCH * NF];   // feat' = 2^13*feat
__device__ __align__(16) __half g_xihi[(size_t)BATCH * NF];
__device__ __align__(16) __half g_mhi [(size_t)BATCH * MIDD];
__device__ __align__(16) __half g_thi [(size_t)NF * MIDD];    // T*64
__device__ __align__(16) __half g_tthi[(size_t)MIDD * NF];    // T^T*64

// ---------------------------------------------------------------------------
// PTX helpers
// ---------------------------------------------------------------------------
__device__ __forceinline__ uint32_t smem_u32(const void* p) {
    uint32_t a;
    asm("{ .reg .u64 t; cvta.to.shared.u64 t, %1; cvt.u32.u64 %0, t; }" : "=r"(a) : "l"(p));
    return a;
}
__device__ __forceinline__ void cp16(uint32_t saddr, const void* gaddr) {
    asm volatile("cp.async.cg.shared.global [%0], [%1], 16;" :: "r"(saddr), "l"(gaddr));
}
__device__ __forceinline__ void cp16z(uint32_t saddr, const void* gaddr, int valid) {
    asm volatile("cp.async.cg.shared.global [%0], [%1], 16, %2;"
                 :: "r"(saddr), "l"(gaddr), "r"(valid ? 16 : 0));
}
__device__ __forceinline__ void cp_commit() { asm volatile("cp.async.commit_group;"); }
__device__ __forceinline__ void cp_wait1()  { asm volatile("cp.async.wait_group 1;" ::: "memory"); }
__device__ __forceinline__ void cp_wait0()  { asm volatile("cp.async.wait_group 0;" ::: "memory"); }

__device__ __forceinline__ void ldsm4(uint32_t r[4], uint32_t a) {
    asm volatile("ldmatrix.sync.aligned.m8n8.x4.shared.b16 {%0,%1,%2,%3}, [%4];"
                 : "=r"(r[0]), "=r"(r[1]), "=r"(r[2]), "=r"(r[3]) : "r"(a));
}
__device__ __forceinline__ void mma16816(float c[4], const uint32_t a[4],
                                         uint32_t b0, uint32_t b1) {
    asm volatile(
        "mma.sync.aligned.m16n8k16.row.col.f32.f16.f16.f32 "
        "{%0,%1,%2,%3}, {%4,%5,%6,%7}, {%8,%9}, {%0,%1,%2,%3};"
        : "+f"(c[0]), "+f"(c[1]), "+f"(c[2]), "+f"(c[3])
        : "r"(a[0]), "r"(a[1]), "r"(a[2]), "r"(a[3]), "r"(b0), "r"(b1));
}

__device__ __forceinline__ uint2 pack4h(float4 v)
{
    uint32_t hb[4];
    float f[4] = {v.x, v.y, v.z, v.w};
    #pragma unroll
    for (int j = 0; j < 4; j++)
        hb[j] = (uint32_t)__half_as_ushort(__float2half_rn(f[j]));
    return make_uint2(hb[0] | (hb[1] << 16), hb[2] | (hb[3] << 16));
}

// ---------------------------------------------------------------------------
// fused: count -> scale^2 + X fp16 pack
// ---------------------------------------------------------------------------
__global__ void splitcount_x_kernel(const float* __restrict__ x)
{
    int b = blockIdx.x;
    const float4* row = (const float4*)(x + (size_t)b * LEN);
    uint2* oh = (uint2*)(g_xhi + (size_t)b * LEN);
    int cnt = 0;
    for (int i = threadIdx.x; i < LEN / 4; i += 256) {
        float4 v = row[i];
        cnt += (v.x != 0.0f) + (v.y != 0.0f) + (v.z != 0.0f) + (v.w != 0.0f);
        oh[i] = pack4h(v);
    }
    #pragma unroll
    for (int o = 16; o > 0; o >>= 1) cnt += __shfl_down_sync(0xffffffffu, cnt, o);
    __shared__ int ws[8];
    if ((threadIdx.x & 31) == 0) ws[threadIdx.x >> 5] = cnt;
    __syncthreads();
    if (threadIdx.x == 0) {
        int t = 0;
        #pragma unroll
        for (int i = 0; i < 8; i++) t += ws[i];
        float s = (float)LEN / (float)(t + 1);
        g_scale2[b] = s * s * ALPHA_INV;
    }
}

__global__ void split_w_kernel(const float* __restrict__ wc, const float* __restrict__ ws)
{
    int i = blockIdx.x * blockDim.x + threadIdx.x;
    if (i >= NF * (LEN / 4)) return;
    int f  = i / (LEN / 4);
    int kq = i % (LEN / 4);
    float4 vc = ((const float4*)wc)[i];
    vc.x *= WSCALE; vc.y *= WSCALE; vc.z *= WSCALE; vc.w *= WSCALE;
    ((uint2*)g_whi)[(size_t)(2 * f) * (LEN / 4) + kq] = pack4h(vc);
    float4 vs = ((const float4*)ws)[i];
    vs.x *= WSCALE; vs.y *= WSCALE; vs.z *= WSCALE; vs.w *= WSCALE;
    ((uint2*)g_whi)[(size_t)(2 * f + 1) * (LEN / 4) + kq] = pack4h(vs);
}

__global__ void split_t_kernel(const float* __restrict__ tmpl)
{
    int i = blockIdx.x * blockDim.x + threadIdx.x;
    if (i >= NF * MIDD) return;
    int r = i / MIDD, c = i % MIDD;
    __half h = __float2half_rn(tmpl[i] * TSCALE);
    g_thi[i] = h;
    g_tthi[(size_t)c * NF + r] = h;
}

// ---------------------------------------------------------------------------
// Fourier HMMA: CTA 128x128, KC=64, single-pass fp16
// ---------------------------------------------------------------------------
#define KC       64
#define TILE_T   (128 * KC * 2)          // 16384 bytes
#define STAGE_F  (2 * TILE_T)            // A, B
#define FSMEM    (2 * STAGE_F)           // 65536

__device__ __forceinline__ void load_chunk(uint32_t sbase, int m0, int n0, int k0, int tid)
{
    const __half* srcs[2] = { g_xhi + (size_t)m0 * LEN, g_whi + (size_t)n0 * LEN };
    #pragma unroll
    for (int t = 0; t < 2; t++) {
        uint32_t tb = sbase + t * TILE_T;
        #pragma unroll
        for (int j = 0; j < 4; j++) {
            int c  = tid + j * 256;
            int r  = c >> 3;
            int kc = c & 7;
            const void* g = srcs[t] + (size_t)r * LEN + k0 + kc * 8;
            uint32_t s = tb + r * 128 + (((uint32_t)(kc ^ (r & 7))) << 4);
            cp16(s, g);
        }
    }
}

__global__ __launch_bounds__(256, 2) void fourier_hmma_kernel()
{
    extern __shared__ char smem_raw[];
    const uint32_t sb = smem_u32(smem_raw);

    const int tid  = threadIdx.x;
    const int wid  = tid >> 5;
    const int lane = tid & 31;
    const int wm   = wid >> 2;
    const int wn   = wid & 3;

    const int TN = NW / 128;             // 33
    const int G  = 8;
    int lin   = blockIdx.y * gridDim.x + blockIdx.x;
    int group = lin / (G * TN);
    int rem   = lin % (G * TN);
    int mt    = group * G + (rem % G);
    int nt    = rem / G;
    const int m0 = mt * 128;
    const int n0 = nt * 128;

    float acc[4][4][4];
    #pragma unroll
    for (int i = 0; i < 4; i++)
        #pragma unroll
        for (int j = 0; j < 4; j++)
            #pragma unroll
            for (int q = 0; q < 4; q++) acc[i][j][q] = 0.0f;

    const int a_r   = lane & 15;
    const int a_k8  = lane >> 4;
    const uint32_t a_x = (uint32_t)(a_r & 7);
    const int bg    = lane >> 3;
    const int b_n   = ((bg >> 1) << 3) + (lane & 7);
    const int b_k8  = bg & 1;
    const uint32_t b_x = (uint32_t)(lane & 7);

    uint32_t a_row_b[4], b_row_b[2];
    #pragma unroll
    for (int mi = 0; mi < 4; mi++) a_row_b[mi] = (uint32_t)(wm * 64 + mi * 16 + a_r) * 128u;
    #pragma unroll
    for (int pr = 0; pr < 2; pr++) b_row_b[pr] = (uint32_t)(wn * 32 + pr * 16 + b_n) * 128u;

    const int NCH = LEN / KC;
    load_chunk(sb, m0, n0, 0, tid);
    cp_commit();

    for (int i = 0; i < NCH; i++) {
        const uint32_t su = sb + (uint32_t)(i & 1) * STAGE_F;
        if (i + 1 < NCH) {
            load_chunk(sb + (uint32_t)((i + 1) & 1) * STAGE_F, m0, n0, (i + 1) * KC, tid);
            cp_commit();
            cp_wait1();
        } else {
            cp_wait0();
        }
        __syncthreads();

        const uint32_t ah_b = su;
        const uint32_t bh_b = su + TILE_T;

        #pragma unroll
        for (int ks = 0; ks < KC / 16; ks++) {
            const uint32_t akc = (uint32_t)(ks * 2 + a_k8);
            const uint32_t bkc = (uint32_t)(ks * 2 + b_k8);
            uint32_t ah[4][4];
            #pragma unroll
            for (int mi = 0; mi < 4; mi++)
                ldsm4(ah[mi], ah_b + a_row_b[mi] + ((akc ^ a_x) << 4));
            uint32_t bh[8];
            #pragma unroll
            for (int pr = 0; pr < 2; pr++)
                ldsm4(&bh[pr * 4], bh_b + b_row_b[pr] + ((bkc ^ b_x) << 4));
            #pragma unroll
            for (int mi = 0; mi < 4; mi++)
                #pragma unroll
                for (int ni = 0; ni < 4; ni++)
                    mma16816(acc[mi][ni], ah[mi], bh[ni * 2], bh[ni * 2 + 1]);
        }
        __syncthreads();
    }

    // epilogue: feat' = s2 * (c^2 + s^2)
    const int qr = lane >> 2;
    const int qc = lane & 3;
    const int fbase = (n0 >> 1) + wn * 16;
    #pragma unroll
    for (int mi = 0; mi < 4; mi++) {
        int row0 = m0 + wm * 64 + mi * 16 + qr;
        int row1 = row0 + 8;
        float s20 = g_scale2[row0];
        float s21 = g_scale2[row1];
        size_t b0 = (size_t)row0 * NF;
        size_t b1 = (size_t)row1 * NF;
        #pragma unroll
        for (int ni = 0; ni < 4; ni++) {
            int f = fbase + ni * 4 + qc;
            float c0 = acc[mi][ni][0], c1 = acc[mi][ni][1];
            float c2 = acc[mi][ni][2], c3 = acc[mi][ni][3];
            g_fhi[b0 + f] = __float2half_rn(s20 * (c0 * c0 + c1 * c1));
            g_fhi[b1 + f] = __float2half_rn(s21 * (c2 * c2 + c3 * c3));
        }
    }
}

// ---------------------------------------------------------------------------
// LISTA HMMA: CTA 128x64, KC=64, single-pass fp16
// ---------------------------------------------------------------------------
#define TILE_A   16384
#define TILE_Bs  8192
#define LSTAGE   (TILE_A + TILE_Bs)       // 24576
#define LSMEM    (2 * LSTAGE)             // 49152

__device__ __forceinline__ void load_chunk_l(
    uint32_t sbase,
    const __half* __restrict__ Ahi, int lda, int m0,
    const __half* __restrict__ Bhi, int ldb, int n0, int N,
    int k0, int K, int tid)
{
    #pragma unroll
    for (int j = 0; j < 4; j++) {
        int c  = tid + j * 256;
        int r  = c >> 3;
        int kc = c & 7;
        int k  = k0 + kc * 8;
        int kv = (k < K);
        uint32_t soff = (uint32_t)r * 128u + (((uint32_t)(kc ^ (r & 7))) << 4);
        cp16z(sbase + soff,
              kv ? (const void*)(Ahi + (size_t)(m0 + r) * lda + k) : (const void*)Ahi, kv);
    }
    #pragma unroll
    for (int j = 0; j < 2; j++) {
        int c  = tid + j * 256;
        int r  = c >> 3;
        int kc = c & 7;
        int k  = k0 + kc * 8;
        int nv = (k < K) && (n0 + r < N);
        uint32_t soff = (uint32_t)r * 128u + (((uint32_t)(kc ^ (r & 7))) << 4);
        cp16z(sbase + TILE_A + soff,
              nv ? (const void*)(Bhi + (size_t)(n0 + r) * ldb + k) : (const void*)Bhi, nv);
    }
}

template<int EPI>
__global__ __launch_bounds__(256, 2) void lista_hmma_kernel(
    const __half* __restrict__ Ahi, int lda,
    const __half* __restrict__ Bhi, int ldb,
    int N, int K,
    __half* __restrict__ Chi, float* __restrict__ Cf, int ldc,
    const __half* __restrict__ Xhi,
    float c0, float c1)
{
    extern __shared__ char smem_raw[];
    const uint32_t sb = smem_u32(smem_raw);

    const int tid  = threadIdx.x;
    const int wid  = tid >> 5;
    const int lane = tid & 31;
    const int wm   = wid >> 1;
    const int wn   = wid & 1;
    const int m0   = blockIdx.y * 128;
    const int n0   = blockIdx.x * 64;

    float acc[2][4][4];
    #pragma unroll
    for (int i = 0; i < 2; i++)
        #pragma unroll
        for (int j = 0; j < 4; j++)
            #pragma unroll
            for (int q = 0; q < 4; q++) acc[i][j][q] = 0.0f;

    const int a_r   = lane & 15;
    const int a_k8  = lane >> 4;
    const uint32_t a_x = (uint32_t)(a_r & 7);
    const int bg    = lane >> 3;
    const int b_n   = ((bg >> 1) << 3) + (lane & 7);
    const int b_k8  = bg & 1;
    const uint32_t b_x = (uint32_t)(lane & 7);

    uint32_t a_row_b[2], b_row_b[2];
    #pragma unroll
    for (int mi = 0; mi < 2; mi++) a_row_b[mi] = (uint32_t)(wm * 32 + mi * 16 + a_r) * 128u;
    #pragma unroll
    for (int pr = 0; pr < 2; pr++) b_row_b[pr] = (uint32_t)(wn * 32 + pr * 16 + b_n) * 128u;

    const int NCH = (K + KC - 1) / KC;
    load_chunk_l(sb, Ahi, lda, m0, Bhi, ldb, n0, N, 0, K, tid);
    cp_commit();

    for (int i = 0; i < NCH; i++) {
        const uint32_t su = sb + (uint32_t)(i & 1) * LSTAGE;
        if (i + 1 < NCH) {
            load_chunk_l(sb + (uint32_t)((i + 1) & 1) * LSTAGE,
                         Ahi, lda, m0, Bhi, ldb, n0, N, (i + 1) * KC, K, tid);
            cp_commit();
            cp_wait1();
        } else {
            cp_wait0();
        }
        __syncthreads();

        const uint32_t ah_b = su;
        const uint32_t bh_b = su + TILE_A;

        #pragma unroll
        for (int ks = 0; ks < KC / 16; ks++) {
            const uint32_t akc = (uint32_t)(ks * 2 + a_k8);
            const uint32_t bkc = (uint32_t)(ks * 2 + b_k8);
            uint32_t ah[2][4];
            #pragma unroll
            for (int mi = 0; mi < 2; mi++)
                ldsm4(ah[mi], ah_b + a_row_b[mi] + ((akc ^ a_x) << 4));
            uint32_t bh[8];
            #pragma unroll
            for (int pr = 0; pr < 2; pr++)
                ldsm4(&bh[pr * 4], bh_b + b_row_b[pr] + ((bkc ^ b_x) << 4));
            #pragma unroll
            for (int mi = 0; mi < 2; mi++)
                #pragma unroll
                for (int ni = 0; ni < 4; ni++)
                    mma16816(acc[mi][ni], ah[mi], bh[ni * 2], bh[ni * 2 + 1]);
        }
        __syncthreads();
    }

    const int qr = lane >> 2;
    const int qc = lane & 3;
    #pragma unroll
    for (int mi = 0; mi < 2; mi++) {
        int rows[2];
        rows[0] = m0 + wm * 32 + mi * 16 + qr;
        rows[1] = rows[0] + 8;
        #pragma unroll
        for (int ni = 0; ni < 4; ni++) {
            int colb = n0 + wn * 32 + ni * 8 + qc * 2;
            #pragma unroll
            for (int h = 0; h < 2; h++) {
                #pragma unroll
                for (int cc = 0; cc < 2; cc++) {
                    int col = colb + cc;
                    if (col >= N) continue;
                    size_t idx = (size_t)rows[h] * ldc + col;
                    float a = acc[mi][ni][h * 2 + cc];
                    float v;
                    if (EPI == 1) {
                        v = fmaxf(C_M0 * a, 0.0f);
                    } else if (EPI == 2) {
                        v = C_XI * a + c0 * __half2float(Xhi[idx]);
                        if (c1 != 0.0f) v += c1 * __half2float(Chi[idx]);
                    } else {
                        float mo = __half2float(Chi[idx]);
                        v = fmaxf(C_MUPD * a + 0.2f * mo, 0.0f);
                    }
                    Chi[idx] = __float2half_rn(v);
                    if (EPI == 1 || EPI == 3) Cf[idx] = v * ALPHA_INV;
                }
            }
        }
    }
}

// ---------------------------------------------------------------------------
// fp32 SIMT GEMM (tail only)
// ---------------------------------------------------------------------------
template<int EPI>
__global__ void gemm64(const float* __restrict__ A, const float* __restrict__ B0,
                       float* __restrict__ C,
                       int N, int K, int lda, int ldb, int ldc,
                       const float* __restrict__ bias)
{
    __shared__ __align__(16) float As [8][68];
    __shared__ __align__(16) float Bs0[8][68];

    const int t  = threadIdx.x;
    const int tx = t & 15;
    const int ty = t >> 4;
    const int m0 = blockIdx.y * 64;
    const int n0 = blockIdx.x * 64;

    float acc0[4][4];
    #pragma unroll
    for (int i = 0; i < 4; i++)
        #pragma unroll
        for (int j = 0; j < 4; j++) acc0[i][j] = 0.0f;

    const int arow = t >> 2;
    const int ak   = (t & 3) * 2;

    for (int k0 = 0; k0 < K; k0 += 8) {
        {
            float2 av = *(const float2*)(A + (size_t)(m0 + arow) * lda + k0 + ak);
            As[ak][arow] = av.x; As[ak + 1][arow] = av.y;
        }
        {
            int n = n0 + arow;
            float2 bv = make_float2(0.0f, 0.0f);
            if (n < N) bv = *(const float2*)(B0 + (size_t)n * ldb + k0 + ak);
            Bs0[ak][arow] = bv.x; Bs0[ak + 1][arow] = bv.y;
        }
        __syncthreads();

        #pragma unroll
        for (int kk = 0; kk < 8; kk++) {
            float4 a = *(const float4*)&As [kk][ty * 4];
            float4 b = *(const float4*)&Bs0[kk][tx * 4];
            float av4[4] = {a.x, a.y, a.z, a.w};
            float bv4[4] = {b.x, b.y, b.z, b.w};
            #pragma unroll
            for (int i = 0; i < 4; i++)
                #pragma unroll
                for (int j = 0; j < 4; j++)
                    acc0[i][j] += av4[i] * bv4[j];
        }
        __syncthreads();
    }

    #pragma unroll
    for (int i = 0; i < 4; i++) {
        int row = m0 + ty * 4 + i;
        #pragma unroll
        for (int j = 0; j < 4; j++) {
            int col = n0 + tx * 4 + j;
            if (col >= N) continue;
            size_t idx = (size_t)row * ldc + col;
            float v;
            if (EPI == 4) {
                v = fmaxf(acc0[i][j] + bias[col], 0.0f);
            } else {
                float z = acc0[i][j] + bias[col];
                v = 1.0f / (1.0f + expf(-z));
            }
            C[idx] = v;
        }
    }
}

// ---------------------------------------------------------------------------
extern "C" void kernel_launch(void* const* d_in, const int* in_sizes, int n_in,
                              void* d_out, int out_size)
{
    const float* input_this = (const float*)d_in[0];
    const float* W_cos = (const float*)d_in[2];
    const float* W_sin = (const float*)d_in[3];
    const float* tmpl  = (const float*)d_in[4];
    const float* W1    = (const float*)d_in[5];
    const float* b1    = (const float*)d_in[6];
    const float* W2    = (const float*)d_in[7];
    const float* b2    = (const float*)d_in[8];
    const float* Wout  = (const float*)d_in[9];
    const float* bout  = (const float*)d_in[10];
    float* out = (float*)d_out;

    float *p_m, *p_h1, *p_h2;
    cudaGetSymbolAddress((void**)&p_m,  g_m);
    cudaGetSymbolAddress((void**)&p_h1, g_h1);
    cudaGetSymbolAddress((void**)&p_h2, g_h2);
    __half *p_fhi, *p_xihi, *p_mhi, *p_thi, *p_tthi;
    cudaGetSymbolAddress((void**)&p_fhi,  g_fhi);
    cudaGetSymbolAddress((void**)&p_xihi, g_xihi);
    cudaGetSymbolAddress((void**)&p_mhi,  g_mhi);
    cudaGetSymbolAddress((void**)&p_thi,  g_thi);
    cudaGetSymbolAddress((void**)&p_tthi, g_tthi);

    dim3 blk(256);

    splitcount_x_kernel<<<BATCH, blk>>>(input_this);
    split_w_kernel<<<(NF * LEN / 4 + 255) / 256, blk>>>(W_cos, W_sin);
    split_t_kernel<<<(NF * MIDD + 255) / 256, blk>>>(tmpl);

    cudaFuncSetAttribute(fourier_hmma_kernel,
                         cudaFuncAttributeMaxDynamicSharedMemorySize, FSMEM);
    cudaFuncSetAttribute(lista_hmma_kernel<1>,
                         cudaFuncAttributeMaxDynamicSharedMemorySize, LSMEM);
    cudaFuncSetAttribute(lista_hmma_kernel<2>,
                         cudaFuncAttributeMaxDynamicSharedMemorySize, LSMEM);
    cudaFuncSetAttribute(lista_hmma_kernel<3>,
                         cudaFuncAttributeMaxDynamicSharedMemorySize, LSMEM);

    fourier_hmma_kernel<<<dim3(NW / 128, BATCH / 128), blk, FSMEM>>>();

    dim3 gMID((MIDD + 63) / 64, BATCH / 128);
    dim3 gNF ((NF + 63) / 64, BATCH / 128);

    lista_hmma_kernel<1><<<gMID, blk, LSMEM>>>(
        p_fhi, NF, p_tthi, NF, MIDD, NF,
        p_mhi, p_m, MIDD, nullptr, 0.f, 0.f);

    for (int it = 0; it < 4; it++) {
        float c0 = (it == 0) ? -1.8f : -1.6f;
        float c1 = (it == 0) ?  0.0f :  0.2f;
        lista_hmma_kernel<2><<<gNF, blk, LSMEM>>>(
            p_mhi, MIDD, p_thi, MIDD, NF, MIDD,
            p_xihi, nullptr, NF, p_fhi, c0, c1);
        lista_hmma_kernel<3><<<gMID, blk, LSMEM>>>(
            p_xihi, NF, p_tthi, NF, MIDD, NF,
            p_mhi, p_m, MIDD, nullptr, 0.f, 0.f);
    }

    gemm64<4><<<dim3((MIDD + 63) / 64, BATCH / 64), blk>>>(
        p_m, W1, p_h1, MIDD, MIDD, MIDD, MIDD, MIDD, b1);
    gemm64<4><<<dim3((PP + 63) / 64, BATCH / 64), blk>>>(
        p_h1, W2, p_h2, PP, MIDD, MIDD, MIDD, PP, b2);
    gemm64<6><<<dim3((PP + 63) / 64, BATCH / 64), blk>>>(
        p_h2, Wout, out, PP, PP, PP, PP, PP, bout);
}

// round 15
// speedup vs baseline: 10.5144x; 1.6042x over previous
#include <cuda_runtime.h>
#include <cuda_fp16.h>
#include <math.h>
#include <stdint.h>

#define BATCH 4096
#define LEN   8192
#define NF    2112
#define MIDD  264
#define PP    88
#define NW    (2 * NF)
#define MPAD  384          // padded row count for tthi / G (multiple of 128)

#define WSCALE    8192.0f
#define ALPHA_INV (1.0f / 8192.0f)
#define TSCALE    64.0f

// ---------------------------------------------------------------------------
// Device scratch
// ---------------------------------------------------------------------------
__device__ float g_scale2[BATCH];
__device__ float g_m  [BATCH * MIDD];       // de-scaled fp32 m (tail input)
__device__ float g_h1 [BATCH * MIDD];
__device__ float g_h2 [BATCH * PP];
__device__ float g_F  [BATCH * MIDD];       // F' = 2^13 * feat@T
__device__ float g_Y  [BATCH * MIDD];       // Y' = 2^13 * y

__device__ __align__(16) __half g_xhi[(size_t)BATCH * LEN];
__device__ __align__(16) __half g_whi[(size_t)NW * LEN];       // W*2^13
__device__ __align__(16) __half g_fhi [(size_t)BATCH * NF];    // feat' = 2^13*feat
__device__ __align__(16) __half g_mA  [(size_t)BATCH * MIDD];  // m' ping
__device__ __align__(16) __half g_mB  [(size_t)BATCH * MIDD];  // m' pong
__device__ __align__(16) __half g_tthi[(size_t)MPAD * NF];     // 64*T^T (rows>=264 zero)
__device__ __align__(16) __half g_G   [(size_t)MPAD * MIDD];   // G' = 64*T^T T

// ---------------------------------------------------------------------------
// PTX helpers
// ---------------------------------------------------------------------------
__device__ __forceinline__ uint32_t smem_u32(const void* p) {
    uint32_t a;
    asm("{ .reg .u64 t; cvta.to.shared.u64 t, %1; cvt.u32.u64 %0, t; }" : "=r"(a) : "l"(p));
    return a;
}
__device__ __forceinline__ void cp16(uint32_t saddr, const void* gaddr) {
    asm volatile("cp.async.cg.shared.global [%0], [%1], 16;" :: "r"(saddr), "l"(gaddr));
}
__device__ __forceinline__ void cp16z(uint32_t saddr, const void* gaddr, int valid) {
    asm volatile("cp.async.cg.shared.global [%0], [%1], 16, %2;"
                 :: "r"(saddr), "l"(gaddr), "r"(valid ? 16 : 0));
}
__device__ __forceinline__ void cp_commit() { asm volatile("cp.async.commit_group;"); }
__device__ __forceinline__ void cp_wait1()  { asm volatile("cp.async.wait_group 1;" ::: "memory"); }
__device__ __forceinline__ void cp_wait0()  { asm volatile("cp.async.wait_group 0;" ::: "memory"); }

__device__ __forceinline__ void ldsm4(uint32_t r[4], uint32_t a) {
    asm volatile("ldmatrix.sync.aligned.m8n8.x4.shared.b16 {%0,%1,%2,%3}, [%4];"
                 : "=r"(r[0]), "=r"(r[1]), "=r"(r[2]), "=r"(r[3]) : "r"(a));
}
__device__ __forceinline__ void mma16816(float c[4], const uint32_t a[4],
                                         uint32_t b0, uint32_t b1) {
    asm volatile(
        "mma.sync.aligned.m16n8k16.row.col.f32.f16.f16.f32 "
        "{%0,%1,%2,%3}, {%4,%5,%6,%7}, {%8,%9}, {%0,%1,%2,%3};"
        : "+f"(c[0]), "+f"(c[1]), "+f"(c[2]), "+f"(c[3])
        : "r"(a[0]), "r"(a[1]), "r"(a[2]), "r"(a[3]), "r"(b0), "r"(b1));
}

__device__ __forceinline__ uint2 pack4h(float4 v)
{
    uint32_t hb[4];
    float f[4] = {v.x, v.y, v.z, v.w};
    #pragma unroll
    for (int j = 0; j < 4; j++)
        hb[j] = (uint32_t)__half_as_ushort(__float2half_rn(f[j]));
    return make_uint2(hb[0] | (hb[1] << 16), hb[2] | (hb[3] << 16));
}

// ---------------------------------------------------------------------------
// fused: count -> scale^2 + X fp16 pack
// ---------------------------------------------------------------------------
__global__ void splitcount_x_kernel(const float* __restrict__ x)
{
    int b = blockIdx.x;
    const float4* row = (const float4*)(x + (size_t)b * LEN);
    uint2* oh = (uint2*)(g_xhi + (size_t)b * LEN);
    int cnt = 0;
    for (int i = threadIdx.x; i < LEN / 4; i += 256) {
        float4 v = row[i];
        cnt += (v.x != 0.0f) + (v.y != 0.0f) + (v.z != 0.0f) + (v.w != 0.0f);
        oh[i] = pack4h(v);
    }
    #pragma unroll
    for (int o = 16; o > 0; o >>= 1) cnt += __shfl_down_sync(0xffffffffu, cnt, o);
    __shared__ int ws[8];
    if ((threadIdx.x & 31) == 0) ws[threadIdx.x >> 5] = cnt;
    __syncthreads();
    if (threadIdx.x == 0) {
        int t = 0;
        #pragma unroll
        for (int i = 0; i < 8; i++) t += ws[i];
        float s = (float)LEN / (float)(t + 1);
        g_scale2[b] = s * s * ALPHA_INV;
    }
}

__global__ void split_w_kernel(const float* __restrict__ wc, const float* __restrict__ ws)
{
    int i = blockIdx.x * blockDim.x + threadIdx.x;
    if (i >= NF * (LEN / 4)) return;
    int f  = i / (LEN / 4);
    int kq = i % (LEN / 4);
    float4 vc = ((const float4*)wc)[i];
    vc.x *= WSCALE; vc.y *= WSCALE; vc.z *= WSCALE; vc.w *= WSCALE;
    ((uint2*)g_whi)[(size_t)(2 * f) * (LEN / 4) + kq] = pack4h(vc);
    float4 vs = ((const float4*)ws)[i];
    vs.x *= WSCALE; vs.y *= WSCALE; vs.z *= WSCALE; vs.w *= WSCALE;
    ((uint2*)g_whi)[(size_t)(2 * f + 1) * (LEN / 4) + kq] = pack4h(vs);
}

// T^T * 64 (rows >= MIDD stay zero-initialized)
__global__ void split_t_kernel(const float* __restrict__ tmpl)
{
    int i = blockIdx.x * blockDim.x + threadIdx.x;
    if (i >= NF * MIDD) return;
    int r = i / MIDD, c = i % MIDD;
    g_tthi[(size_t)c * NF + r] = __float2half_rn(tmpl[i] * TSCALE);
}

// ---------------------------------------------------------------------------
// Fourier HMMA: CTA 128x128, KC=64, single-pass fp16
// ---------------------------------------------------------------------------
#define KC       64
#define TILE_T   (128 * KC * 2)
#define STAGE_F  (2 * TILE_T)
#define FSMEM    (2 * STAGE_F)

__device__ __forceinline__ void load_chunk(uint32_t sbase, int m0, int n0, int k0, int tid)
{
    const __half* srcs[2] = { g_xhi + (size_t)m0 * LEN, g_whi + (size_t)n0 * LEN };
    #pragma unroll
    for (int t = 0; t < 2; t++) {
        uint32_t tb = sbase + t * TILE_T;
        #pragma unroll
        for (int j = 0; j < 4; j++) {
            int c  = tid + j * 256;
            int r  = c >> 3;
            int kc = c & 7;
            const void* g = srcs[t] + (size_t)r * LEN + k0 + kc * 8;
            uint32_t s = tb + r * 128 + (((uint32_t)(kc ^ (r & 7))) << 4);
            cp16(s, g);
        }
    }
}

__global__ __launch_bounds__(256, 2) void fourier_hmma_kernel()
{
    extern __shared__ char smem_raw[];
    const uint32_t sb = smem_u32(smem_raw);

    const int tid  = threadIdx.x;
    const int wid  = tid >> 5;
    const int lane = tid & 31;
    const int wm   = wid >> 2;
    const int wn   = wid & 3;

    const int TN = NW / 128;
    const int G  = 8;
    int lin   = blockIdx.y * gridDim.x + blockIdx.x;
    int group = lin / (G * TN);
    int rem   = lin % (G * TN);
    int mt    = group * G + (rem % G);
    int nt    = rem / G;
    const int m0 = mt * 128;
    const int n0 = nt * 128;

    float acc[4][4][4];
    #pragma unroll
    for (int i = 0; i < 4; i++)
        #pragma unroll
        for (int j = 0; j < 4; j++)
            #pragma unroll
            for (int q = 0; q < 4; q++) acc[i][j][q] = 0.0f;

    const int a_r   = lane & 15;
    const int a_k8  = lane >> 4;
    const uint32_t a_x = (uint32_t)(a_r & 7);
    const int bg    = lane >> 3;
    const int b_n   = ((bg >> 1) << 3) + (lane & 7);
    const int b_k8  = bg & 1;
    const uint32_t b_x = (uint32_t)(lane & 7);

    uint32_t a_row_b[4], b_row_b[2];
    #pragma unroll
    for (int mi = 0; mi < 4; mi++) a_row_b[mi] = (uint32_t)(wm * 64 + mi * 16 + a_r) * 128u;
    #pragma unroll
    for (int pr = 0; pr < 2; pr++) b_row_b[pr] = (uint32_t)(wn * 32 + pr * 16 + b_n) * 128u;

    const int NCH = LEN / KC;
    load_chunk(sb, m0, n0, 0, tid);
    cp_commit();

    for (int i = 0; i < NCH; i++) {
        const uint32_t su = sb + (uint32_t)(i & 1) * STAGE_F;
        if (i + 1 < NCH) {
            load_chunk(sb + (uint32_t)((i + 1) & 1) * STAGE_F, m0, n0, (i + 1) * KC, tid);
            cp_commit();
            cp_wait1();
        } else {
            cp_wait0();
        }
        __syncthreads();

        const uint32_t ah_b = su;
        const uint32_t bh_b = su + TILE_T;

        #pragma unroll
        for (int ks = 0; ks < KC / 16; ks++) {
            const uint32_t akc = (uint32_t)(ks * 2 + a_k8);
            const uint32_t bkc = (uint32_t)(ks * 2 + b_k8);
            uint32_t ah[4][4];
            #pragma unroll
            for (int mi = 0; mi < 4; mi++)
                ldsm4(ah[mi], ah_b + a_row_b[mi] + ((akc ^ a_x) << 4));
            uint32_t bh[8];
            #pragma unroll
            for (int pr = 0; pr < 2; pr++)
                ldsm4(&bh[pr * 4], bh_b + b_row_b[pr] + ((bkc ^ b_x) << 4));
            #pragma unroll
            for (int mi = 0; mi < 4; mi++)
                #pragma unroll
                for (int ni = 0; ni < 4; ni++)
                    mma16816(acc[mi][ni], ah[mi], bh[ni * 2], bh[ni * 2 + 1]);
        }
        __syncthreads();
    }

    const int qr = lane >> 2;
    const int qc = lane & 3;
    const int fbase = (n0 >> 1) + wn * 16;
    #pragma unroll
    for (int mi = 0; mi < 4; mi++) {
        int row0 = m0 + wm * 64 + mi * 16 + qr;
        int row1 = row0 + 8;
        float s20 = g_scale2[row0];
        float s21 = g_scale2[row1];
        size_t b0 = (size_t)row0 * NF;
        size_t b1 = (size_t)row1 * NF;
        #pragma unroll
        for (int ni = 0; ni < 4; ni++) {
            int f = fbase + ni * 4 + qc;
            float c0 = acc[mi][ni][0], c1 = acc[mi][ni][1];
            float c2 = acc[mi][ni][2], c3 = acc[mi][ni][3];
            g_fhi[b0 + f] = __float2half_rn(s20 * (c0 * c0 + c1 * c1));
            g_fhi[b1 + f] = __float2half_rn(s21 * (c2 * c2 + c3 * c3));
        }
    }
}

// ---------------------------------------------------------------------------
// LISTA-family HMMA: CTA 128x64, KC=64, single-pass fp16
// EPI 1 (F):  Cf = acc/64 (=F'), Chi = relu((10/64)*acc) (=m0')
// EPI 2 (G):  Chi = fp16(acc/64)  (=G' = 64*T^T T)
// EPI 3 (IT): vy = (1.6/64)*acc + c0*Fp + c1*Yp ; Yp = vy
//             vm = relu(-8*vy + 0.2*Min) ; Chi = vm ; Cf = vm*2^-13
// ---------------------------------------------------------------------------
#define TILE_A   16384
#define TILE_Bs  8192
#define LSTAGE   (TILE_A + TILE_Bs)
#define LSMEM    (2 * LSTAGE)

__device__ __forceinline__ void load_chunk_l(
    uint32_t sbase,
    const __half* __restrict__ Ahi, int lda, int m0,
    const __half* __restrict__ Bhi, int ldb, int n0, int N,
    int k0, int K, int tid)
{
    #pragma unroll
    for (int j = 0; j < 4; j++) {
        int c  = tid + j * 256;
        int r  = c >> 3;
        int kc = c & 7;
        int k  = k0 + kc * 8;
        int kv = (k < K);
        uint32_t soff = (uint32_t)r * 128u + (((uint32_t)(kc ^ (r & 7))) << 4);
        cp16z(sbase + soff,
              kv ? (const void*)(Ahi + (size_t)(m0 + r) * lda + k) : (const void*)Ahi, kv);
    }
    #pragma unroll
    for (int j = 0; j < 2; j++) {
        int c  = tid + j * 256;
        int r  = c >> 3;
        int kc = c & 7;
        int k  = k0 + kc * 8;
        int nv = (k < K) && (n0 + r < N);
        uint32_t soff = (uint32_t)r * 128u + (((uint32_t)(kc ^ (r & 7))) << 4);
        cp16z(sbase + TILE_A + soff,
              nv ? (const void*)(Bhi + (size_t)(n0 + r) * ldb + k) : (const void*)Bhi, nv);
    }
}

template<int EPI>
__global__ __launch_bounds__(256, 2) void lista_hmma_kernel(
    const __half* __restrict__ Ahi, int lda,
    const __half* __restrict__ Bhi, int ldb,
    int N, int K,
    __half* __restrict__ Chi, float* __restrict__ Cf, int ldc,
    const float* __restrict__ Fp, float* __restrict__ Yp,
    const __half* __restrict__ Min,
    float c0, float c1)
{
    extern __shared__ char smem_raw[];
    const uint32_t sb = smem_u32(smem_raw);

    const int tid  = threadIdx.x;
    const int wid  = tid >> 5;
    const int lane = tid & 31;
    const int wm   = wid >> 1;
    const int wn   = wid & 1;
    const int m0   = blockIdx.y * 128;
    const int n0   = blockIdx.x * 64;

    float acc[2][4][4];
    #pragma unroll
    for (int i = 0; i < 2; i++)
        #pragma unroll
        for (int j = 0; j < 4; j++)
            #pragma unroll
            for (int q = 0; q < 4; q++) acc[i][j][q] = 0.0f;

    const int a_r   = lane & 15;
    const int a_k8  = lane >> 4;
    const uint32_t a_x = (uint32_t)(a_r & 7);
    const int bg    = lane >> 3;
    const int b_n   = ((bg >> 1) << 3) + (lane & 7);
    const int b_k8  = bg & 1;
    const uint32_t b_x = (uint32_t)(lane & 7);

    uint32_t a_row_b[2], b_row_b[2];
    #pragma unroll
    for (int mi = 0; mi < 2; mi++) a_row_b[mi] = (uint32_t)(wm * 32 + mi * 16 + a_r) * 128u;
    #pragma unroll
    for (int pr = 0; pr < 2; pr++) b_row_b[pr] = (uint32_t)(wn * 32 + pr * 16 + b_n) * 128u;

    const int NCH = (K + KC - 1) / KC;
    load_chunk_l(sb, Ahi, lda, m0, Bhi, ldb, n0, N, 0, K, tid);
    cp_commit();

    for (int i = 0; i < NCH; i++) {
        const uint32_t su = sb + (uint32_t)(i & 1) * LSTAGE;
        if (i + 1 < NCH) {
            load_chunk_l(sb + (uint32_t)((i + 1) & 1) * LSTAGE,
                         Ahi, lda, m0, Bhi, ldb, n0, N, (i + 1) * KC, K, tid);
            cp_commit();
            cp_wait1();
        } else {
            cp_wait0();
        }
        __syncthreads();

        const uint32_t ah_b = su;
        const uint32_t bh_b = su + TILE_A;

        #pragma unroll
        for (int ks = 0; ks < KC / 16; ks++) {
            const uint32_t akc = (uint32_t)(ks * 2 + a_k8);
            const uint32_t bkc = (uint32_t)(ks * 2 + b_k8);
            uint32_t ah[2][4];
            #pragma unroll
            for (int mi = 0; mi < 2; mi++)
                ldsm4(ah[mi], ah_b + a_row_b[mi] + ((akc ^ a_x) << 4));
            uint32_t bh[8];
            #pragma unroll
            for (int pr = 0; pr < 2; pr++)
                ldsm4(&bh[pr * 4], bh_b + b_row_b[pr] + ((bkc ^ b_x) << 4));
            #pragma unroll
            for (int mi = 0; mi < 2; mi++)
                #pragma unroll
                for (int ni = 0; ni < 4; ni++)
                    mma16816(acc[mi][ni], ah[mi], bh[ni * 2], bh[ni * 2 + 1]);
        }
        __syncthreads();
    }

    const int qr = lane >> 2;
    const int qc = lane & 3;
    #pragma unroll
    for (int mi = 0; mi < 2; mi++) {
        int rows[2];
        rows[0] = m0 + wm * 32 + mi * 16 + qr;
        rows[1] = rows[0] + 8;
        #pragma unroll
        for (int ni = 0; ni < 4; ni++) {
            int colb = n0 + wn * 32 + ni * 8 + qc * 2;
            #pragma unroll
            for (int h = 0; h < 2; h++) {
                #pragma unroll
                for (int cc = 0; cc < 2; cc++) {
                    int col = colb + cc;
                    if (col >= N) continue;
                    size_t idx = (size_t)rows[h] * ldc + col;
                    float a = acc[mi][ni][h * 2 + cc];
                    if (EPI == 1) {
                        Cf[idx] = a * (1.0f / 64.0f);
                        Chi[idx] = __float2half_rn(fmaxf((10.0f / 64.0f) * a, 0.0f));
                    } else if (EPI == 2) {
                        Chi[idx] = __float2half_rn(a * (1.0f / 64.0f));
                    } else {
                        float vy = (1.6f / 64.0f) * a + c0 * Fp[idx];
                        if (c1 != 0.0f) vy += c1 * Yp[idx];
                        Yp[idx] = vy;
                        float vm = fmaxf(-8.0f * vy + 0.2f * __half2float(Min[idx]), 0.0f);
                        Chi[idx] = __float2half_rn(vm);
                        Cf[idx] = vm * ALPHA_INV;
                    }
                }
            }
        }
    }
}

// ---------------------------------------------------------------------------
// fp32 SIMT GEMM (tail only)
// ---------------------------------------------------------------------------
template<int EPI>
__global__ void gemm64(const float* __restrict__ A, const float* __restrict__ B0,
                       float* __restrict__ C,
                       int N, int K, int lda, int ldb, int ldc,
                       const float* __restrict__ bias)
{
    __shared__ __align__(16) float As [8][68];
    __shared__ __align__(16) float Bs0[8][68];

    const int t  = threadIdx.x;
    const int tx = t & 15;
    const int ty = t >> 4;
    const int m0 = blockIdx.y * 64;
    const int n0 = blockIdx.x * 64;

    float acc0[4][4];
    #pragma unroll
    for (int i = 0; i < 4; i++)
        #pragma unroll
        for (int j = 0; j < 4; j++) acc0[i][j] = 0.0f;

    const int arow = t >> 2;
    const int ak   = (t & 3) * 2;

    for (int k0 = 0; k0 < K; k0 += 8) {
        {
            float2 av = *(const float2*)(A + (size_t)(m0 + arow) * lda + k0 + ak);
            As[ak][arow] = av.x; As[ak + 1][arow] = av.y;
        }
        {
            int n = n0 + arow;
            float2 bv = make_float2(0.0f, 0.0f);
            if (n < N) bv = *(const float2*)(B0 + (size_t)n * ldb + k0 + ak);
            Bs0[ak][arow] = bv.x; Bs0[ak + 1][arow] = bv.y;
        }
        __syncthreads();

        #pragma unroll
        for (int kk = 0; kk < 8; kk++) {
            float4 a = *(const float4*)&As [kk][ty * 4];
            float4 b = *(const float4*)&Bs0[kk][tx * 4];
            float av4[4] = {a.x, a.y, a.z, a.w};
            float bv4[4] = {b.x, b.y, b.z, b.w};
            #pragma unroll
            for (int i = 0; i < 4; i++)
                #pragma unroll
                for (int j = 0; j < 4; j++)
                    acc0[i][j] += av4[i] * bv4[j];
        }
        __syncthreads();
    }

    #pragma unroll
    for (int i = 0; i < 4; i++) {
        int row = m0 + ty * 4 + i;
        #pragma unroll
        for (int j = 0; j < 4; j++) {
            int col = n0 + tx * 4 + j;
            if (col >= N) continue;
            size_t idx = (size_t)row * ldc + col;
            float v;
            if (EPI == 4) {
                v = fmaxf(acc0[i][j] + bias[col], 0.0f);
            } else {
                float z = acc0[i][j] + bias[col];
                v = 1.0f / (1.0f + expf(-z));
            }
            C[idx] = v;
        }
    }
}

// ---------------------------------------------------------------------------
extern "C" void kernel_launch(void* const* d_in, const int* in_sizes, int n_in,
                              void* d_out, int out_size)
{
    const float* input_this = (const float*)d_in[0];
    const float* W_cos = (const float*)d_in[2];
    const float* W_sin = (const float*)d_in[3];
    const float* tmpl  = (const float*)d_in[4];
    const float* W1    = (const float*)d_in[5];
    const float* b1    = (const float*)d_in[6];
    const float* W2    = (const float*)d_in[7];
    const float* b2    = (const float*)d_in[8];
    const float* Wout  = (const float*)d_in[9];
    const float* bout  = (const float*)d_in[10];
    float* out = (float*)d_out;

    float *p_m, *p_h1, *p_h2, *p_F, *p_Y;
    cudaGetSymbolAddress((void**)&p_m,  g_m);
    cudaGetSymbolAddress((void**)&p_h1, g_h1);
    cudaGetSymbolAddress((void**)&p_h2, g_h2);
    cudaGetSymbolAddress((void**)&p_F,  g_F);
    cudaGetSymbolAddress((void**)&p_Y,  g_Y);
    __half *p_fhi, *p_mA, *p_mB, *p_tthi, *p_G;
    cudaGetSymbolAddress((void**)&p_fhi,  g_fhi);
    cudaGetSymbolAddress((void**)&p_mA,   g_mA);
    cudaGetSymbolAddress((void**)&p_mB,   g_mB);
    cudaGetSymbolAddress((void**)&p_tthi, g_tthi);
    cudaGetSymbolAddress((void**)&p_G,    g_G);

    dim3 blk(256);

    splitcount_x_kernel<<<BATCH, blk>>>(input_this);
    split_w_kernel<<<(NF * LEN / 4 + 255) / 256, blk>>>(W_cos, W_sin);
    split_t_kernel<<<(NF * MIDD + 255) / 256, blk>>>(tmpl);

    cudaFuncSetAttribute(fourier_hmma_kernel,
                         cudaFuncAttributeMaxDynamicSharedMemorySize, FSMEM);
    cudaFuncSetAttribute(lista_hmma_kernel<1>,
                         cudaFuncAttributeMaxDynamicSharedMemorySize, LSMEM);
    cudaFuncSetAttribute(lista_hmma_kernel<2>,
                         cudaFuncAttributeMaxDynamicSharedMemorySize, LSMEM);
    cudaFuncSetAttribute(lista_hmma_kernel<3>,
                         cudaFuncAttributeMaxDynamicSharedMemorySize, LSMEM);

    // G' = 64 * T^T T   (A rows padded to 384; rows>=264 are zeros)
    lista_hmma_kernel<2><<<dim3((MIDD + 63) / 64, MPAD / 128), blk, LSMEM>>>(
        p_tthi, NF, p_tthi, NF, MIDD, NF,
        p_G, nullptr, MIDD, nullptr, nullptr, nullptr, 0.f, 0.f);

    fourier_hmma_kernel<<<dim3(NW / 128, BATCH / 128), blk, FSMEM>>>();

    dim3 gMID((MIDD + 63) / 64, BATCH / 128);

    // F' = 2^13 feat@T ; m0' = relu(10F)*2^13
    lista_hmma_kernel<1><<<gMID, blk, LSMEM>>>(
        p_fhi, NF, p_tthi, NF, MIDD, NF,
        p_mA, p_F, MIDD, nullptr, nullptr, nullptr, 0.f, 0.f);

    // 4 fused iterations on [4096x264]@[264x264]
    __half* mi = p_mA;
    __half* mo = p_mB;
    for (int it = 0; it < 4; it++) {
        float c0 = (it == 0) ? -1.8f : -1.6f;
        float c1 = (it == 0) ?  0.0f :  0.2f;
        lista_hmma_kernel<3><<<gMID, blk, LSMEM>>>(
            mi, MIDD, p_G, MIDD, MIDD, MIDD,
            mo, p_m, MIDD, p_F, p_Y, mi, c0, c1);
        __half* tmp = mi; mi = mo; mo = tmp;
    }

    // fp32 tail
    gemm64<4><<<dim3((MIDD + 63) / 64, BATCH / 64), blk>>>(
        p_m, W1, p_h1, MIDD, MIDD, MIDD, MIDD, MIDD, b1);
    gemm64<4><<<dim3((PP + 63) / 64, BATCH / 64), blk>>>(
        p_h1, W2, p_h2, PP, MIDD, MIDD, MIDD, PP, b2);
    gemm64<6><<<dim3((PP + 63) / 64, BATCH / 64), blk>>>(
        p_h2, Wout, out, PP, PP, PP, PP, PP, bout);
}